// round 1
// baseline (speedup 1.0000x reference)
#include <cuda_runtime.h>
#include <math.h>
#include <stdio.h>

// ---------------- problem constants ----------------
#define Bq   4
#define Sq   512
#define Nq   256
#define Eq   42
#define Pq   256
#define Kq   3
#define Lq   4
#define HBq  768
#define DTq  20
#define DIq  20
#define Gq   256
#define NLq  2
#define Rq   97
#define NHq  4
#define D0q  808          // HB+DT+DI
#define BANKq 1576        // D0 + G*(NL+1)
#define BANK4q 6304       // 4*BANK
#define BANK5q 7880       // 5*BANK
#define DHq  394          // BANK/NH
#define Mlstm (Bq*Pq*Kq)        // 3072
#define MlstmT (Mlstm*Lq)       // 12288
#define BPq  (Bq*Pq)            // 1024

// ---------------- scratch (static device memory; no allocations allowed) ----------------
__device__ float g_enc   [Bq*Sq*D0q];
__device__ float g_feats [Bq*Nq*BANKq];
__device__ float g_tmp   [Bq*Nq*D0q];
__device__ float g_x1    [Bq*Nq*Gq];
__device__ float g_xq    [Bq*Nq*Gq];
__device__ float g_xk    [Bq*Nq*Gq];
__device__ float g_xv    [Bq*Nq*Gq];
__device__ float g_att   [Bq*Nq*Nq];
__device__ float g_pf    [MlstmT*BANKq];
__device__ float g_ih    [(size_t)MlstmT*BANK4q];
__device__ float g_hh    [(size_t)Mlstm*BANK4q];
__device__ float g_h     [Mlstm*BANKq];
__device__ float g_c     [Mlstm*BANKq];
__device__ float g_hs0   [MlstmT*BANKq];
__device__ float g_hs1   [MlstmT*BANKq];
__device__ float g_pe    [Mlstm*BANKq];
__device__ float g_hf    [BPq*BANKq];
__device__ float g_tf    [BPq*BANKq];
__device__ float g_query [BPq*BANKq];
__device__ float g_q     [BPq*BANKq];
__device__ float g_k     [Mlstm*BANKq];
__device__ float g_v     [Mlstm*BANKq];
__device__ float g_ctx   [BPq*BANKq];
__device__ float g_pinfo [BPq*BANKq];
__device__ int   g_validany[BPq];
__device__ float g_of    [BPq*BANK5q];
__device__ float g_hid   [BPq*BANK5q];

// ---------------- generic tiled SGEMM: C = act(alpha*A@op(B) + bias) + resid ----------------
// A: MxK (lda), B: KxN (ldb) or B: NxK (ldb) if TRANSB, C: MxN (ldc). Batched via grid.z.
#define TS 128
#define KS 8

template <bool TRANSB>
__global__ void __launch_bounds__(256, 2)
gemm_kernel(const float* __restrict__ A, const float* __restrict__ B,
            const float* __restrict__ bias, const float* __restrict__ resid,
            float* __restrict__ C,
            int M, int N, int K,
            int lda, int ldb, int ldc, int ldr,
            long sA, long sB, long sC, long sR,
            float alpha, int act)
{
    int bz = blockIdx.z;
    A += bz * sA;
    B += bz * sB;
    C += bz * sC;
    if (resid) resid += bz * sR;

    int row0 = blockIdx.y * TS;
    int col0 = blockIdx.x * TS;

    __shared__ float As[KS][TS];
    __shared__ float Bs[KS][TS + 4];

    int tid = threadIdx.x;
    int tx = tid & 15, ty = tid >> 4;

    float acc[8][8];
#pragma unroll
    for (int i = 0; i < 8; i++)
#pragma unroll
        for (int j = 0; j < 8; j++) acc[i][j] = 0.f;

    for (int k0 = 0; k0 < K; k0 += KS) {
#pragma unroll
        for (int l = 0; l < 4; l++) {
            int idx = tid + l * 256;
            int m = idx >> 3, kk = idx & 7;
            int gr = row0 + m, gk = k0 + kk;
            As[kk][m] = (gr < M && gk < K) ? A[(long)gr * lda + gk] : 0.f;
        }
#pragma unroll
        for (int l = 0; l < 4; l++) {
            int idx = tid + l * 256;
            if (TRANSB) {
                int n = idx >> 3, kk = idx & 7;
                int gn = col0 + n, gk = k0 + kk;
                Bs[kk][n] = (gn < N && gk < K) ? B[(long)gn * ldb + gk] : 0.f;
            } else {
                int kk = idx >> 7, n = idx & 127;
                int gn = col0 + n, gk = k0 + kk;
                Bs[kk][n] = (gn < N && gk < K) ? B[(long)gk * ldb + gn] : 0.f;
            }
        }
        __syncthreads();
#pragma unroll
        for (int kk = 0; kk < KS; kk++) {
            float a[8], b[8];
#pragma unroll
            for (int i = 0; i < 8; i++) a[i] = As[kk][ty + 16 * i];
#pragma unroll
            for (int j = 0; j < 8; j++) b[j] = Bs[kk][tx + 16 * j];
#pragma unroll
            for (int i = 0; i < 8; i++)
#pragma unroll
                for (int j = 0; j < 8; j++)
                    acc[i][j] = fmaf(a[i], b[j], acc[i][j]);
        }
        __syncthreads();
    }

#pragma unroll
    for (int i = 0; i < 8; i++) {
        int r = row0 + ty + 16 * i;
        if (r >= M) continue;
#pragma unroll
        for (int j = 0; j < 8; j++) {
            int cc = col0 + tx + 16 * j;
            if (cc >= N) continue;
            float v = acc[i][j] * alpha;
            if (bias) v += bias[cc];
            if (act == 1) v = fmaxf(v, 0.f);
            if (resid) v += resid[(long)r * ldr + cc];
            C[(long)r * ldc + cc] = v;
        }
    }
}

static void gemm(bool transB,
                 const float* A, const float* B, const float* bias, const float* resid, float* C,
                 int M, int N, int K, int lda, int ldb, int ldc, int ldr,
                 long sA, long sB, long sC, long sR, int batch, float alpha, int act)
{
    dim3 grid((N + TS - 1) / TS, (M + TS - 1) / TS, batch);
    if (transB)
        gemm_kernel<true><<<grid, 256>>>(A, B, bias, resid, C, M, N, K, lda, ldb, ldc, ldr, sA, sB, sC, sR, alpha, act);
    else
        gemm_kernel<false><<<grid, 256>>>(A, B, bias, resid, C, M, N, K, lda, ldb, ldc, ldr, sA, sB, sC, sR, alpha, act);
}

// ---------------- small custom kernels ----------------

__global__ void build_enc_kernel(const float* __restrict__ eo, const int* __restrict__ etype,
                                 const int* __restrict__ eid, const float* __restrict__ temb,
                                 const float* __restrict__ iemb, float* __restrict__ enc)
{
    int bs = blockIdx.x;
    const float* src = eo + (long)bs * HBq;
    float* dst = enc + (long)bs * D0q;
    int ty = etype[bs], idv = eid[bs];
    for (int j = threadIdx.x; j < D0q; j += blockDim.x) {
        float v;
        if (j < HBq)            v = src[j];
        else if (j < HBq + DTq) v = temb[ty * DTq + (j - HBq)];
        else                    v = iemb[idv * DIq + (j - HBq - DTq)];
        dst[j] = v;
    }
}

__global__ void softmax256_kernel(float* __restrict__ x)
{
    int row = blockIdx.x;
    int tid = threadIdx.x;
    float v = x[(long)row * 256 + tid];
    __shared__ float red[8];
    int lane = tid & 31, warp = tid >> 5;
    float m = v;
#pragma unroll
    for (int o = 16; o > 0; o >>= 1) m = fmaxf(m, __shfl_xor_sync(0xffffffffu, m, o));
    if (lane == 0) red[warp] = m;
    __syncthreads();
    if (tid == 0) {
        float mm = red[0];
        for (int w = 1; w < 8; w++) mm = fmaxf(mm, red[w]);
        red[0] = mm;
    }
    __syncthreads();
    float mx = red[0];
    float e = expf(v - mx);
    float s = e;
#pragma unroll
    for (int o = 16; o > 0; o >>= 1) s += __shfl_xor_sync(0xffffffffu, s, o);
    __shared__ float red2[8];
    if (lane == 0) red2[warp] = s;
    __syncthreads();
    if (tid == 0) {
        float ss = 0.f;
        for (int w = 0; w < 8; w++) ss += red2[w];
        red2[0] = ss;
    }
    __syncthreads();
    x[(long)row * 256 + tid] = e / red2[0];
}

__global__ void gather_pf_kernel(const float* __restrict__ feats, const int* __restrict__ nodes,
                                 float* __restrict__ pf)
{
    int row = blockIdx.x;                 // 0..12287 (= i*L + t)
    int b = row / (Pq * Kq * Lq);
    int node = nodes[row];
    const float4* src = (const float4*)(feats + ((long)b * Nq + node) * BANKq);
    float4* dst = (float4*)(pf + (long)row * BANKq);
    for (int j = threadIdx.x; j < BANKq / 4; j += blockDim.x) dst[j] = src[j];
}

__device__ __forceinline__ float sigmoidf_(float x) { return 1.f / (1.f + expf(-x)); }

__global__ void lstm_cell_kernel(const float* __restrict__ ih, const float* __restrict__ hh,
                                 float* __restrict__ h, float* __restrict__ c,
                                 float* __restrict__ hs, int t)
{
    int i = blockIdx.y;
    int j = blockIdx.x * blockDim.x + threadIdx.x;
    if (j >= BANKq) return;
    const float* g = ih + ((long)i * Lq + t) * BANK4q;
    float gi = g[j], gf = g[BANKq + j], gg = g[2 * BANKq + j], go = g[3 * BANKq + j];
    float cp = 0.f;
    if (t > 0) {
        const float* hr = hh + (long)i * BANK4q;
        gi += hr[j]; gf += hr[BANKq + j]; gg += hr[2 * BANKq + j]; go += hr[3 * BANKq + j];
        cp = c[(long)i * BANKq + j];
    }
    float cn = sigmoidf_(gf) * cp + sigmoidf_(gi) * tanhf(gg);
    float hn = sigmoidf_(go) * tanhf(cn);
    c[(long)i * BANKq + j] = cn;
    h[(long)i * BANKq + j] = hn;
    hs[((long)i * Lq + t) * BANKq + j] = hn;
}

__global__ void maxpool_kernel(const float* __restrict__ hs, const int* __restrict__ lens,
                               float* __restrict__ pe)
{
    int i = blockIdx.y;
    int j = blockIdx.x * blockDim.x + threadIdx.x;
    if (j >= BANKq) return;
    int len = lens[i];
    float m = -1e9f;
    const float* base = hs + (long)i * Lq * BANKq + j;
    for (int t = 0; t < Lq; t++)
        if (t < len) m = fmaxf(m, base[(long)t * BANKq]);
    pe[(long)i * BANKq + j] = (len > 0) ? m : 0.f;
}

__global__ void gather_ht_kernel(const float* __restrict__ feats, const int* __restrict__ htp,
                                 float* __restrict__ hf, float* __restrict__ tf,
                                 float* __restrict__ query)
{
    int bp = blockIdx.x;
    int b = bp / Pq;
    int h0 = htp[bp * 2 + 0], t0 = htp[bp * 2 + 1];
    h0 = (h0 == 0) ? 0 : h0 - 1;
    t0 = (t0 == 0) ? 0 : t0 - 1;
    const float* hs = feats + ((long)b * Nq + (Nq - Eq) + h0) * BANKq;
    const float* ts = feats + ((long)b * Nq + (Nq - Eq) + t0) * BANKq;
    for (int j = threadIdx.x; j < BANKq; j += blockDim.x) {
        float hv = hs[j], tv = ts[j];
        hf[(long)bp * BANKq + j] = hv;
        tf[(long)bp * BANKq + j] = tv;
        query[(long)bp * BANKq + j] = hv - tv;
    }
}

__global__ void mha_attn_kernel(const float* __restrict__ q, const float* __restrict__ k,
                                const float* __restrict__ v, const int* __restrict__ plens,
                                const float* __restrict__ rmask,
                                float* __restrict__ ctx, int* __restrict__ validany)
{
    int bp = blockIdx.x;
    int tid = threadIdx.x;
    int warp = tid >> 5, lane = tid & 31;
    __shared__ float sc[NHq][Kq];
    __shared__ float aw[NHq][Kq];
    __shared__ int vm[Kq];
    if (tid < Kq) vm[tid] = (rmask[bp] > 0.f && plens[bp * Kq + tid] > 0) ? 1 : 0;
    __syncthreads();
    // 12 warps: warp = h*3 + kk
    {
        int h = warp / Kq, kk = warp % Kq;
        const float* qh = q + (long)bp * BANKq + h * DHq;
        const float* kh = k + ((long)bp * Kq + kk) * BANKq + h * DHq;
        float s = 0.f;
        for (int d = lane; d < DHq; d += 32) s += qh[d] * kh[d];
#pragma unroll
        for (int o = 16; o > 0; o >>= 1) s += __shfl_xor_sync(0xffffffffu, s, o);
        if (lane == 0) {
            s = s / sqrtf((float)DHq);
            sc[h][kk] = vm[kk] ? s : -1e9f;
        }
    }
    __syncthreads();
    if (tid < NHq) {
        int h = tid;
        float m = fmaxf(fmaxf(sc[h][0], sc[h][1]), sc[h][2]);
        float e0 = expf(sc[h][0] - m), e1 = expf(sc[h][1] - m), e2 = expf(sc[h][2] - m);
        float s = e0 + e1 + e2;
        aw[h][0] = e0 / s; aw[h][1] = e1 / s; aw[h][2] = e2 / s;
    }
    if (tid == 0) validany[bp] = (vm[0] | vm[1] | vm[2]);
    __syncthreads();
    for (int j = tid; j < BANKq; j += blockDim.x) {
        int h = j / DHq;
        const float* vb = v + (long)bp * Kq * BANKq + j;
        float r = aw[h][0] * vb[0] + aw[h][1] * vb[BANKq] + aw[h][2] * vb[2 * BANKq];
        ctx[(long)bp * BANKq + j] = r;
    }
}

__global__ void build_of_kernel(const float* __restrict__ hf, const float* __restrict__ tf,
                                const float* __restrict__ pinfo, const int* __restrict__ validany,
                                float* __restrict__ of)
{
    int bp = blockIdx.x;
    int va = validany[bp];
    const float* hr = hf + (long)bp * BANKq;
    const float* tr = tf + (long)bp * BANKq;
    const float* pr = pinfo + (long)bp * BANKq;
    float* o = of + (long)bp * BANK5q;
    for (int j = threadIdx.x; j < BANK5q; j += blockDim.x) {
        int seg = j / BANKq, jj = j - seg * BANKq;
        float v;
        if (seg == 0)      v = hr[jj];
        else if (seg == 1) v = tr[jj];
        else if (seg == 2) v = fabsf(hr[jj] - tr[jj]);
        else if (seg == 3) v = hr[jj] * tr[jj];
        else               v = va ? pr[jj] : 0.f;
        o[j] = v;
    }
}

// ---------------- orchestration ----------------
extern "C" void kernel_launch(void* const* d_in, const int* in_sizes, int n_in,
                              void* d_out, int out_size)
{
    const float* encoder_outputs = (const float*)d_in[0];
    const int*   entity_type     = (const int*)  d_in[1];
    const int*   entity_id       = (const int*)  d_in[2];
    const float* sub2words       = (const float*)d_in[3];
    const float* adj             = (const float*)d_in[4];
    const int*   h_t_pairs       = (const int*)  d_in[5];
    const float* rel_mask        = (const float*)d_in[6];
    const int*   path_nodes      = (const int*)  d_in[7];
    const int*   path_lens       = (const int*)  d_in[8];
    const float* type_emb        = (const float*)d_in[9];
    const float* id_emb          = (const float*)d_in[10];
    const float* gcn0_W          = (const float*)d_in[11];
    const float* gcn0_b          = (const float*)d_in[12];
    const float* gcn_W           = (const float*)d_in[13];
    const float* gcn_b           = (const float*)d_in[14];
    const float* attn_Wq         = (const float*)d_in[15];
    const float* attn_Wk         = (const float*)d_in[16];
    const float* attn_Wv         = (const float*)d_in[17];
    const float* lstm_Wih        = (const float*)d_in[18];
    const float* lstm_Whh        = (const float*)d_in[19];
    const float* lstm_b          = (const float*)d_in[20];
    const float* mha_inW         = (const float*)d_in[21];
    const float* mha_inb         = (const float*)d_in[22];
    const float* mha_outW        = (const float*)d_in[23];
    const float* mha_outb        = (const float*)d_in[24];
    const float* pred_W          = (const float*)d_in[25];
    const float* pred_b          = (const float*)d_in[26];
    const float* mW              = (const float*)d_in[27];
    const float* mb              = (const float*)d_in[28];
    const float* bW              = (const float*)d_in[29];
    const float* bb              = (const float*)d_in[30];
    float* out = (float*)d_out;

    void* p;
#define SYMADDR(var, sym) cudaGetSymbolAddress(&p, sym); float* var = (float*)p;
    SYMADDR(enc,   g_enc);    SYMADDR(feats, g_feats);  SYMADDR(tmp,   g_tmp);
    SYMADDR(x1,    g_x1);     SYMADDR(xq,    g_xq);     SYMADDR(xk,    g_xk);
    SYMADDR(xv,    g_xv);     SYMADDR(att,   g_att);    SYMADDR(pf,    g_pf);
    SYMADDR(ih,    g_ih);     SYMADDR(hh,    g_hh);     SYMADDR(hbuf,  g_h);
    SYMADDR(cbuf,  g_c);      SYMADDR(hs0,   g_hs0);    SYMADDR(hs1,   g_hs1);
    SYMADDR(pe,    g_pe);     SYMADDR(hf,    g_hf);     SYMADDR(tf,    g_tf);
    SYMADDR(query, g_query);  SYMADDR(qb,    g_q);      SYMADDR(kb,    g_k);
    SYMADDR(vb,    g_v);      SYMADDR(ctx,   g_ctx);    SYMADDR(pinfo, g_pinfo);
    SYMADDR(of,    g_of);     SYMADDR(hid,   g_hid);
    cudaGetSymbolAddress(&p, g_validany); int* validany = (int*)p;
#undef SYMADDR

    // 1) enc = concat(encoder_outputs, type_emb[...], id_emb[...])
    build_enc_kernel<<<Bq * Sq, 256>>>(encoder_outputs, entity_type, entity_id, type_emb, id_emb, enc);

    // 2) x0 = sub2words @ enc  -> feats[:, :, 0:808]
    gemm(false, sub2words, enc, nullptr, nullptr, feats,
         Nq, D0q, Sq, Sq, D0q, BANKq, 0,
         (long)Nq * Sq, (long)Sq * D0q, (long)Nq * BANKq, 0, Bq, 1.f, 0);

    // 3) tmp = adj @ x0
    gemm(false, adj, feats, nullptr, nullptr, tmp,
         Nq, D0q, Nq, Nq, BANKq, D0q, 0,
         (long)Nq * Nq, (long)Nq * BANKq, (long)Nq * D0q, 0, Bq, 1.f, 0);

    // 4) xg0 = tmp @ gcn0_W + gcn0_b -> feats[:, :, 808:1064]
    gemm(false, tmp, gcn0_W, gcn0_b, nullptr, feats + 808,
         Nq, Gq, D0q, D0q, Gq, BANKq, 0,
         (long)Nq * D0q, 0, (long)Nq * BANKq, 0, Bq, 1.f, 0);

    // 5) GCN + graph-attention layers
    int xoff[NLq]   = {808, 1064};
    int outoff[NLq] = {1064, 1320};
    for (int l = 0; l < NLq; l++) {
        const float* x = feats + xoff[l];
        // t2 = adj @ x
        gemm(false, adj, x, nullptr, nullptr, tmp,
             Nq, Gq, Nq, Nq, BANKq, Gq, 0,
             (long)Nq * Nq, (long)Nq * BANKq, (long)Nq * Gq, 0, Bq, 1.f, 0);
        // x1 = relu(t2 @ gcn_W[l] + gcn_b[l])
        gemm(false, tmp, gcn_W + (long)l * Gq * Gq, gcn_b + l * Gq, nullptr, x1,
             Nq, Gq, Gq, Gq, Gq, Gq, 0,
             (long)Nq * Gq, 0, (long)Nq * Gq, 0, Bq, 1.f, 1);
        // xq = x @ attn_Wq[l]
        gemm(false, x, attn_Wq + (long)l * Gq * Gq, nullptr, nullptr, xq,
             Nq, Gq, Gq, BANKq, Gq, Gq, 0,
             (long)Nq * BANKq, 0, (long)Nq * Gq, 0, Bq, 1.f, 0);
        // xk = x1 @ attn_Wk[l]
        gemm(false, x1, attn_Wk + (long)l * Gq * Gq, nullptr, nullptr, xk,
             Nq, Gq, Gq, Gq, Gq, Gq, 0,
             (long)Nq * Gq, 0, (long)Nq * Gq, 0, Bq, 1.f, 0);
        // xv = x1 @ attn_Wv[l]
        gemm(false, x1, attn_Wv + (long)l * Gq * Gq, nullptr, nullptr, xv,
             Nq, Gq, Gq, Gq, Gq, Gq, 0,
             (long)Nq * Gq, 0, (long)Nq * Gq, 0, Bq, 1.f, 0);
        // att = softmax(xq @ xk^T * 1/16)
        gemm(true, xq, xk, nullptr, nullptr, att,
             Nq, Nq, Gq, Gq, Gq, Nq, 0,
             (long)Nq * Gq, (long)Nq * Gq, (long)Nq * Nq, 0, Bq, 0.0625f, 0);
        softmax256_kernel<<<Bq * Nq, 256>>>(att);
        // x_next = x1 + relu(att @ xv) -> feats slice
        gemm(false, att, xv, nullptr, x1, feats + outoff[l],
             Nq, Gq, Nq, Nq, Gq, BANKq, Gq,
             (long)Nq * Nq, (long)Nq * Gq, (long)Nq * BANKq, (long)Nq * Gq, Bq, 1.f, 1);
    }

    // 6) gather paths
    gather_pf_kernel<<<MlstmT, 256>>>(feats, path_nodes, pf);

    // 7) two LSTM layers
    const float* Xin = pf;
    float* hsbuf[2] = {hs0, hs1};
    for (int layer = 0; layer < 2; layer++) {
        const float* Wih = lstm_Wih + (long)layer * BANK4q * BANKq;
        const float* Whh = lstm_Whh + (long)layer * BANK4q * BANKq;
        const float* bL  = lstm_b + (long)layer * BANK4q;
        // ih = Xin @ Wih^T + b for all timesteps at once
        gemm(true, Xin, Wih, bL, nullptr, ih,
             MlstmT, BANK4q, BANKq, BANKq, BANKq, BANK4q, 0,
             0, 0, 0, 0, 1, 1.f, 0);
        for (int t = 0; t < Lq; t++) {
            if (t > 0)
                gemm(true, hbuf, Whh, nullptr, nullptr, hh,
                     Mlstm, BANK4q, BANKq, BANKq, BANKq, BANK4q, 0,
                     0, 0, 0, 0, 1, 1.f, 0);
            dim3 grid((BANKq + 255) / 256, Mlstm);
            lstm_cell_kernel<<<grid, 256>>>(ih, hh, hbuf, cbuf, hsbuf[layer], t);
        }
        Xin = hsbuf[layer];
    }

    // 8) masked max-pool over time
    {
        dim3 grid((BANKq + 255) / 256, Mlstm);
        maxpool_kernel<<<grid, 256>>>(hs1, path_lens, pe);
    }

    // 9) h_f, t_f, query
    gather_ht_kernel<<<BPq, 256>>>(feats, h_t_pairs, hf, tf, query);

    // 10-11) q/k/v projections
    gemm(true, query, mha_inW, mha_inb, nullptr, qb,
         BPq, BANKq, BANKq, BANKq, BANKq, BANKq, 0, 0, 0, 0, 0, 1, 1.f, 0);
    gemm(true, pe, mha_inW + (long)BANKq * BANKq, mha_inb + BANKq, nullptr, kb,
         Mlstm, BANKq, BANKq, BANKq, BANKq, BANKq, 0, 0, 0, 0, 0, 1, 1.f, 0);
    gemm(true, pe, mha_inW + 2L * BANKq * BANKq, mha_inb + 2 * BANKq, nullptr, vb,
         Mlstm, BANKq, BANKq, BANKq, BANKq, BANKq, 0, 0, 0, 0, 0, 1, 1.f, 0);

    // 12) tiny attention over K=3 paths
    mha_attn_kernel<<<BPq, 384>>>(qb, kb, vb, path_lens, rel_mask, ctx, validany);

    // 13) pinfo = ctx @ mha_outW^T + mha_outb (masking applied in build_of)
    gemm(true, ctx, mha_outW, mha_outb, nullptr, pinfo,
         BPq, BANKq, BANKq, BANKq, BANKq, BANKq, 0, 0, 0, 0, 0, 1, 1.f, 0);

    // 14) of = [h_f, t_f, |h_f - t_f|, h_f*t_f, pinfo_masked]
    build_of_kernel<<<BPq, 256>>>(hf, tf, pinfo, validany, of);

    // 15) hid = relu(of @ pred_W + pred_b)
    gemm(false, of, pred_W, pred_b, nullptr, hid,
         BPq, BANK5q, BANK5q, BANK5q, BANK5q, BANK5q, 0, 0, 0, 0, 0, 1, 1.f, 1);

    // 16) outputs
    gemm(false, hid, mW, mb, nullptr, out,
         BPq, Rq, BANK5q, BANK5q, Rq, Rq, 0, 0, 0, 0, 0, 1, 1.f, 0);
    gemm(false, hid, bW, bb, nullptr, out + (long)BPq * Rq,
         BPq, 2, BANK5q, BANK5q, 2, 2, 0, 0, 0, 0, 0, 1, 1.f, 0);
}

// round 2
// speedup vs baseline: 1.6198x; 1.6198x over previous
#include <cuda_runtime.h>
#include <cuda_bf16.h>
#include <math.h>
#include <stdio.h>

// ---------------- problem constants ----------------
#define Bq   4
#define Sq   512
#define Nq   256
#define Eq   42
#define Pq   256
#define Kq   3
#define Lq   4
#define HBq  768
#define DTq  20
#define DIq  20
#define Gq   256
#define NLq  2
#define Rq   97
#define NHq  4
#define D0q  808          // HB+DT+DI
#define BANKq 1576        // D0 + G*(NL+1)
#define BANK4q 6304       // 4*BANK
#define BANK5q 7880       // 5*BANK
#define DHq  394          // BANK/NH
#define Mlstm (Bq*Pq*Kq)        // 3072
#define MlstmT (Mlstm*Lq)       // 12288
#define BPq  (Bq*Pq)            // 1024

typedef __nv_bfloat16 bf16;
typedef __nv_bfloat162 bf162;

// ---------------- scratch (static device memory; no allocations allowed) ----------------
__device__ float g_enc   [Bq*Sq*D0q];
__device__ float g_feats [Bq*Nq*BANKq];
__device__ float g_tmp   [Bq*Nq*D0q];
__device__ float g_x1    [Bq*Nq*Gq];
__device__ float g_xq    [Bq*Nq*Gq];
__device__ float g_xk    [Bq*Nq*Gq];
__device__ float g_xv    [Bq*Nq*Gq];
__device__ float g_att   [Bq*Nq*Nq];
__device__ float g_ih    [(size_t)MlstmT*BANK4q];
__device__ float g_hh    [(size_t)Mlstm*BANK4q];
__device__ float g_c     [Mlstm*BANKq];
__device__ float g_hs0   [MlstmT*BANKq];
__device__ float g_hs1   [MlstmT*BANKq];
__device__ float g_pe    [Mlstm*BANKq];
__device__ float g_hf    [BPq*BANKq];
__device__ float g_tf    [BPq*BANKq];
__device__ float g_query [BPq*BANKq];
__device__ float g_q     [BPq*BANKq];
__device__ float g_k     [Mlstm*BANKq];
__device__ float g_v     [Mlstm*BANKq];
__device__ float g_ctx   [BPq*BANKq];
__device__ float g_pinfo [BPq*BANKq];
__device__ int   g_validany[BPq];
__device__ float g_of    [BPq*BANK5q];
__device__ float g_hid   [BPq*BANK5q];

// bf16 split scratch
__device__ bf16 g_ah  [(size_t)MlstmT*BANKq];     // activations hi (12288x1576)
__device__ bf16 g_al  [(size_t)MlstmT*BANKq];     // activations lo
__device__ bf16 g_sh  [(size_t)Mlstm*BANKq];      // small activations hi (3072x1576)
__device__ bf16 g_sl  [(size_t)Mlstm*BANKq];
__device__ bf16 g_w1h [(size_t)BANK4q*BANKq];     // weight buffer 1 (6304x1576)
__device__ bf16 g_w1l [(size_t)BANK4q*BANKq];
__device__ bf16 g_w2h [(size_t)BANK4q*BANKq];     // weight buffer 2
__device__ bf16 g_w2l [(size_t)BANK4q*BANKq];
__device__ bf16 g_wph [(size_t)BANK5q*BANK5q];    // pred weight transposed (7880x7880)
__device__ bf16 g_wpl [(size_t)BANK5q*BANK5q];

// ================= fp32 tiled GEMMs (for small ops) =================
#define TS 128
#define KS 8

template <bool TRANSB>
__global__ void __launch_bounds__(256, 2)
gemm_kernel(const float* __restrict__ A, const float* __restrict__ B,
            const float* __restrict__ bias, const float* __restrict__ resid,
            float* __restrict__ C,
            int M, int N, int K,
            int lda, int ldb, int ldc, int ldr,
            long sA, long sB, long sC, long sR,
            float alpha, int act)
{
    int bz = blockIdx.z;
    A += bz * sA; B += bz * sB; C += bz * sC;
    if (resid) resid += bz * sR;

    int row0 = blockIdx.y * TS;
    int col0 = blockIdx.x * TS;

    __shared__ float As[KS][TS];
    __shared__ float Bs[KS][TS + 4];

    int tid = threadIdx.x;
    int tx = tid & 15, ty = tid >> 4;

    float acc[8][8];
#pragma unroll
    for (int i = 0; i < 8; i++)
#pragma unroll
        for (int j = 0; j < 8; j++) acc[i][j] = 0.f;

    for (int k0 = 0; k0 < K; k0 += KS) {
#pragma unroll
        for (int l = 0; l < 4; l++) {
            int idx = tid + l * 256;
            int m = idx >> 3, kk = idx & 7;
            int gr = row0 + m, gk = k0 + kk;
            As[kk][m] = (gr < M && gk < K) ? A[(long)gr * lda + gk] : 0.f;
        }
#pragma unroll
        for (int l = 0; l < 4; l++) {
            int idx = tid + l * 256;
            if (TRANSB) {
                int n = idx >> 3, kk = idx & 7;
                int gn = col0 + n, gk = k0 + kk;
                Bs[kk][n] = (gn < N && gk < K) ? B[(long)gn * ldb + gk] : 0.f;
            } else {
                int kk = idx >> 7, n = idx & 127;
                int gn = col0 + n, gk = k0 + kk;
                Bs[kk][n] = (gn < N && gk < K) ? B[(long)gk * ldb + gn] : 0.f;
            }
        }
        __syncthreads();
#pragma unroll
        for (int kk = 0; kk < KS; kk++) {
            float a[8], b[8];
#pragma unroll
            for (int i = 0; i < 8; i++) a[i] = As[kk][ty + 16 * i];
#pragma unroll
            for (int j = 0; j < 8; j++) b[j] = Bs[kk][tx + 16 * j];
#pragma unroll
            for (int i = 0; i < 8; i++)
#pragma unroll
                for (int j = 0; j < 8; j++)
                    acc[i][j] = fmaf(a[i], b[j], acc[i][j]);
        }
        __syncthreads();
    }

#pragma unroll
    for (int i = 0; i < 8; i++) {
        int r = row0 + ty + 16 * i;
        if (r >= M) continue;
#pragma unroll
        for (int j = 0; j < 8; j++) {
            int cc = col0 + tx + 16 * j;
            if (cc >= N) continue;
            float v = acc[i][j] * alpha;
            if (bias) v += bias[cc];
            if (act == 1) v = fmaxf(v, 0.f);
            if (resid) v += resid[(long)r * ldr + cc];
            C[(long)r * ldc + cc] = v;
        }
    }
}

// 64x64 tile variant, better occupancy for small M/N
template <bool TRANSB>
__global__ void __launch_bounds__(256)
gemm64_kernel(const float* __restrict__ A, const float* __restrict__ B,
              const float* __restrict__ bias, const float* __restrict__ resid,
              float* __restrict__ C,
              int M, int N, int K,
              int lda, int ldb, int ldc, int ldr,
              long sA, long sB, long sC, long sR,
              float alpha, int act)
{
    int bz = blockIdx.z;
    A += bz * sA; B += bz * sB; C += bz * sC;
    if (resid) resid += bz * sR;

    int row0 = blockIdx.y * 64;
    int col0 = blockIdx.x * 64;

    __shared__ float As[16][64 + 1];
    __shared__ float Bs[16][64 + 1];

    int tid = threadIdx.x;
    int tx = tid & 15, ty = tid >> 4;

    float acc[4][4];
#pragma unroll
    for (int i = 0; i < 4; i++)
#pragma unroll
        for (int j = 0; j < 4; j++) acc[i][j] = 0.f;

    for (int k0 = 0; k0 < K; k0 += 16) {
#pragma unroll
        for (int l = 0; l < 4; l++) {
            int idx = tid + l * 256;
            int m = idx >> 4, kk = idx & 15;
            int gr = row0 + m, gk = k0 + kk;
            As[kk][m] = (gr < M && gk < K) ? A[(long)gr * lda + gk] : 0.f;
        }
#pragma unroll
        for (int l = 0; l < 4; l++) {
            int idx = tid + l * 256;
            if (TRANSB) {
                int n = idx >> 4, kk = idx & 15;
                int gn = col0 + n, gk = k0 + kk;
                Bs[kk][n] = (gn < N && gk < K) ? B[(long)gn * ldb + gk] : 0.f;
            } else {
                int kk = idx >> 6, n = idx & 63;
                int gn = col0 + n, gk = k0 + kk;
                Bs[kk][n] = (gn < N && gk < K) ? B[(long)gk * ldb + gn] : 0.f;
            }
        }
        __syncthreads();
#pragma unroll
        for (int kk = 0; kk < 16; kk++) {
            float a[4], b[4];
#pragma unroll
            for (int i = 0; i < 4; i++) a[i] = As[kk][ty + 16 * i];
#pragma unroll
            for (int j = 0; j < 4; j++) b[j] = Bs[kk][tx + 16 * j];
#pragma unroll
            for (int i = 0; i < 4; i++)
#pragma unroll
                for (int j = 0; j < 4; j++)
                    acc[i][j] = fmaf(a[i], b[j], acc[i][j]);
        }
        __syncthreads();
    }

#pragma unroll
    for (int i = 0; i < 4; i++) {
        int r = row0 + ty + 16 * i;
        if (r >= M) continue;
#pragma unroll
        for (int j = 0; j < 4; j++) {
            int cc = col0 + tx + 16 * j;
            if (cc >= N) continue;
            float v = acc[i][j] * alpha;
            if (bias) v += bias[cc];
            if (act == 1) v = fmaxf(v, 0.f);
            if (resid) v += resid[(long)r * ldr + cc];
            C[(long)r * ldc + cc] = v;
        }
    }
}

static void gemm(bool transB,
                 const float* A, const float* B, const float* bias, const float* resid, float* C,
                 int M, int N, int K, int lda, int ldb, int ldc, int ldr,
                 long sA, long sB, long sC, long sR, int batch, float alpha, int act)
{
    if (M <= 256) {
        dim3 grid((N + 63) / 64, (M + 63) / 64, batch);
        if (transB)
            gemm64_kernel<true><<<grid, 256>>>(A, B, bias, resid, C, M, N, K, lda, ldb, ldc, ldr, sA, sB, sC, sR, alpha, act);
        else
            gemm64_kernel<false><<<grid, 256>>>(A, B, bias, resid, C, M, N, K, lda, ldb, ldc, ldr, sA, sB, sC, sR, alpha, act);
    } else {
        dim3 grid((N + TS - 1) / TS, (M + TS - 1) / TS, batch);
        if (transB)
            gemm_kernel<true><<<grid, 256>>>(A, B, bias, resid, C, M, N, K, lda, ldb, ldc, ldr, sA, sB, sC, sR, alpha, act);
        else
            gemm_kernel<false><<<grid, 256>>>(A, B, bias, resid, C, M, N, K, lda, ldb, ldc, ldr, sA, sB, sC, sR, alpha, act);
    }
}

// ================= bf16 split-precision tensor-core GEMM =================
// C(MxN) = A(MxK) @ B(NxK)^T + bias, with A = Ah+Al, B = Bh+Bl (bf16 splits).
// acc += Ah*Bh + Ah*Bl + Al*Bh  (lo*lo dropped, ~2^-18 relative)
#define LDSB 40   // padded row stride in bf16 (80B -> conflict-free ldmatrix)

#define MMA_BF16(d, a, b) asm volatile( \
    "mma.sync.aligned.m16n8k16.row.col.f32.bf16.bf16.f32 " \
    "{%0,%1,%2,%3}, {%4,%5,%6,%7}, {%8,%9}, {%0,%1,%2,%3};" \
    : "+f"((d)[0]), "+f"((d)[1]), "+f"((d)[2]), "+f"((d)[3]) \
    : "r"((a)[0]), "r"((a)[1]), "r"((a)[2]), "r"((a)[3]), "r"((b)[0]), "r"((b)[1]))

#define LDSM4(r, addr) asm volatile( \
    "ldmatrix.sync.aligned.m8n8.x4.shared.b16 {%0,%1,%2,%3}, [%4];" \
    : "=r"((r)[0]), "=r"((r)[1]), "=r"((r)[2]), "=r"((r)[3]) : "r"(addr))

__global__ void __launch_bounds__(256)
gemm_bf16_kernel(const bf16* __restrict__ Ah, const bf16* __restrict__ Al,
                 const bf16* __restrict__ Bh, const bf16* __restrict__ Bl,
                 const float* __restrict__ bias, float* __restrict__ C,
                 int M, int N, int K, int act)
{
    __shared__ __align__(16) bf16 As[2][128][LDSB];
    __shared__ __align__(16) bf16 Bs[2][128][LDSB];

    int tid = threadIdx.x;
    int warp = tid >> 5, lane = tid & 31;
    int wm = (warp & 1) * 64;    // warp row offset in tile
    int wn = (warp >> 1) * 32;   // warp col offset in tile
    long row0 = (long)blockIdx.y * 128;
    long col0 = (long)blockIdx.x * 128;

    float acc[4][4][4];
#pragma unroll
    for (int a = 0; a < 4; a++)
#pragma unroll
        for (int b = 0; b < 4; b++)
#pragma unroll
            for (int c = 0; c < 4; c++) acc[a][b][c] = 0.f;

    unsigned aBase = (unsigned)__cvta_generic_to_shared(&As[0][0][0]);
    unsigned bBase = (unsigned)__cvta_generic_to_shared(&Bs[0][0][0]);
    const unsigned HOFF = 128 * LDSB * 2;  // bytes between hi and lo planes

    int am_r = (lane & 7) + ((lane >> 3) & 1) * 8;
    int a_c8 = ((lane >> 4) & 1) * 8;
    int b_r  = (lane & 7) + ((lane >> 4) & 1) * 8;
    int b_c8 = ((lane >> 3) & 1) * 8;

    for (int k0 = 0; k0 < K; k0 += 32) {
        // ---- load A tile (128x32, hi+lo) as uints ----
#pragma unroll
        for (int i = 0; i < 8; i++) {
            int linear = tid + i * 256;      // uint index, 2048 total
            int r = linear >> 4;
            int kk = (linear & 15) * 2;
            long gr = row0 + r; int gk = k0 + kk;
            unsigned vh = 0, vl = 0;
            if (gr < M && gk < K) {
                size_t off = (size_t)gr * K + gk;
                vh = *(const unsigned*)(Ah + off);
                vl = *(const unsigned*)(Al + off);
            }
            *(unsigned*)&As[0][r][kk] = vh;
            *(unsigned*)&As[1][r][kk] = vl;
        }
        // ---- load B tile (128 cols x 32 k, B stored [N][K]) ----
#pragma unroll
        for (int i = 0; i < 8; i++) {
            int linear = tid + i * 256;
            int r = linear >> 4;
            int kk = (linear & 15) * 2;
            long gn = col0 + r; int gk = k0 + kk;
            unsigned vh = 0, vl = 0;
            if (gn < N && gk < K) {
                size_t off = (size_t)gn * K + gk;
                vh = *(const unsigned*)(Bh + off);
                vl = *(const unsigned*)(Bl + off);
            }
            *(unsigned*)&Bs[0][r][kk] = vh;
            *(unsigned*)&Bs[1][r][kk] = vl;
        }
        __syncthreads();

#pragma unroll
        for (int ks = 0; ks < 2; ks++) {
            int kb = ks * 16;
            unsigned bh[2][4], bl[2][4];
#pragma unroll
            for (int p = 0; p < 2; p++) {
                unsigned addr = bBase + (unsigned)(((wn + p * 16 + b_r) * LDSB + kb + b_c8) * 2);
                LDSM4(bh[p], addr);
                LDSM4(bl[p], addr + HOFF);
            }
#pragma unroll
            for (int mi = 0; mi < 4; mi++) {
                unsigned ah[4], al[4];
                unsigned addr = aBase + (unsigned)(((wm + mi * 16 + am_r) * LDSB + kb + a_c8) * 2);
                LDSM4(ah, addr);
                LDSM4(al, addr + HOFF);
#pragma unroll
                for (int ni = 0; ni < 4; ni++) {
                    unsigned* ph = &bh[ni >> 1][(ni & 1) * 2];
                    unsigned* pl = &bl[ni >> 1][(ni & 1) * 2];
                    MMA_BF16(acc[mi][ni], ah, ph);
                    MMA_BF16(acc[mi][ni], ah, pl);
                    MMA_BF16(acc[mi][ni], al, ph);
                }
            }
        }
        __syncthreads();
    }

    // ---- epilogue ----
#pragma unroll
    for (int mi = 0; mi < 4; mi++) {
#pragma unroll
        for (int ni = 0; ni < 4; ni++) {
            long r = row0 + wm + mi * 16 + (lane >> 2);
            long c = col0 + wn + ni * 8 + (lane & 3) * 2;
#pragma unroll
            for (int half = 0; half < 2; half++) {
                long rr = r + half * 8;
                if (rr >= M) continue;
#pragma unroll
                for (int e = 0; e < 2; e++) {
                    long cc = c + e;
                    if (cc >= N) continue;
                    float v = acc[mi][ni][half * 2 + e];
                    if (bias) v += bias[cc];
                    if (act == 1) v = fmaxf(v, 0.f);
                    C[(size_t)rr * N + cc] = v;
                }
            }
        }
    }
}

static void gemm_bf16(const bf16* Ah, const bf16* Al, const bf16* Bh, const bf16* Bl,
                      const float* bias, float* C, int M, int N, int K, int act)
{
    dim3 grid((N + 127) / 128, (M + 127) / 128);
    gemm_bf16_kernel<<<grid, 256>>>(Ah, Al, Bh, Bl, bias, C, M, N, K, act);
}

// ================= conversion kernels =================
__device__ __forceinline__ void split1(float f, bf16& h, bf16& l)
{
    h = __float2bfloat16(f);
    l = __float2bfloat16(f - __bfloat162float(h));
}

__global__ void split_kernel(const float* __restrict__ x, bf16* __restrict__ hi,
                             bf16* __restrict__ lo, size_t n4)
{
    size_t i = (size_t)blockIdx.x * blockDim.x + threadIdx.x;
    if (i >= n4) return;
    float4 f = ((const float4*)x)[i];
    bf16 h0, l0, h1, l1, h2, l2, h3, l3;
    split1(f.x, h0, l0); split1(f.y, h1, l1); split1(f.z, h2, l2); split1(f.w, h3, l3);
    bf162 vh0; vh0.x = h0; vh0.y = h1;
    bf162 vh1; vh1.x = h2; vh1.y = h3;
    bf162 vl0; vl0.x = l0; vl0.y = l1;
    bf162 vl1; vl1.x = l2; vl1.y = l3;
    ((bf162*)hi)[i * 2] = vh0; ((bf162*)hi)[i * 2 + 1] = vh1;
    ((bf162*)lo)[i * 2] = vl0; ((bf162*)lo)[i * 2 + 1] = vl1;
}

static void split(const float* x, bf16* hi, bf16* lo, size_t n)
{
    size_t n4 = n / 4;
    split_kernel<<<(unsigned)((n4 + 255) / 256), 256>>>(x, hi, lo, n4);
}

// transpose + split: B (KxN fp32) -> Th/Tl ([N][K] bf16)
__global__ void transpose_split_kernel(const float* __restrict__ B, bf16* __restrict__ Th,
                                       bf16* __restrict__ Tl, int K, int N)
{
    __shared__ float tile[32][33];
    int k0 = blockIdx.y * 32, n0 = blockIdx.x * 32;
    int tx = threadIdx.x, ty = threadIdx.y;  // 32 x 8
#pragma unroll
    for (int i = 0; i < 32; i += 8) {
        int k = k0 + ty + i, n = n0 + tx;
        tile[ty + i][tx] = (k < K && n < N) ? B[(size_t)k * N + n] : 0.f;
    }
    __syncthreads();
#pragma unroll
    for (int i = 0; i < 32; i += 8) {
        int n = n0 + ty + i, k = k0 + tx;
        if (n < N && k < K) {
            float f = tile[tx][ty + i];
            bf16 h, l; split1(f, h, l);
            Th[(size_t)n * K + k] = h;
            Tl[(size_t)n * K + k] = l;
        }
    }
}

// ---------------- small custom kernels ----------------
__global__ void build_enc_kernel(const float* __restrict__ eo, const int* __restrict__ etype,
                                 const int* __restrict__ eid, const float* __restrict__ temb,
                                 const float* __restrict__ iemb, float* __restrict__ enc)
{
    int bs = blockIdx.x;
    const float* src = eo + (long)bs * HBq;
    float* dst = enc + (long)bs * D0q;
    int ty = etype[bs], idv = eid[bs];
    for (int j = threadIdx.x; j < D0q; j += blockDim.x) {
        float v;
        if (j < HBq)            v = src[j];
        else if (j < HBq + DTq) v = temb[ty * DTq + (j - HBq)];
        else                    v = iemb[idv * DIq + (j - HBq - DTq)];
        dst[j] = v;
    }
}

__global__ void softmax256_kernel(float* __restrict__ x)
{
    int row = blockIdx.x;
    int tid = threadIdx.x;
    float v = x[(long)row * 256 + tid];
    __shared__ float red[8];
    int lane = tid & 31, warp = tid >> 5;
    float m = v;
#pragma unroll
    for (int o = 16; o > 0; o >>= 1) m = fmaxf(m, __shfl_xor_sync(0xffffffffu, m, o));
    if (lane == 0) red[warp] = m;
    __syncthreads();
    if (tid == 0) {
        float mm = red[0];
        for (int w = 1; w < 8; w++) mm = fmaxf(mm, red[w]);
        red[0] = mm;
    }
    __syncthreads();
    float mx = red[0];
    float e = expf(v - mx);
    float s = e;
#pragma unroll
    for (int o = 16; o > 0; o >>= 1) s += __shfl_xor_sync(0xffffffffu, s, o);
    __shared__ float red2[8];
    if (lane == 0) red2[warp] = s;
    __syncthreads();
    if (tid == 0) {
        float ss = 0.f;
        for (int w = 0; w < 8; w++) ss += red2[w];
        red2[0] = ss;
    }
    __syncthreads();
    x[(long)row * 256 + tid] = e / red2[0];
}

// gather path features directly into split bf16
__global__ void gather_pf_split_kernel(const float* __restrict__ feats, const int* __restrict__ nodes,
                                       bf16* __restrict__ hi, bf16* __restrict__ lo)
{
    int row = blockIdx.x;                 // 0..12287
    int b = row / (Pq * Kq * Lq);
    int node = nodes[row];
    const float* src = feats + ((size_t)b * Nq + node) * BANKq;
    size_t base = (size_t)row * BANKq;
    for (int j = threadIdx.x; j < BANKq; j += blockDim.x) {
        bf16 h, l; split1(src[j], h, l);
        hi[base + j] = h;
        lo[base + j] = l;
    }
}

__device__ __forceinline__ float sigmoidf_(float x) { return 1.f / (1.f + expf(-x)); }

__global__ void lstm_cell_kernel(const float* __restrict__ ih, const float* __restrict__ hh,
                                 bf16* __restrict__ h_hi, bf16* __restrict__ h_lo,
                                 float* __restrict__ c, float* __restrict__ hs, int t)
{
    int i = blockIdx.y;
    int j = blockIdx.x * blockDim.x + threadIdx.x;
    if (j >= BANKq) return;
    const float* g = ih + ((size_t)i * Lq + t) * BANK4q;
    float gi = g[j], gf = g[BANKq + j], gg = g[2 * BANKq + j], go = g[3 * BANKq + j];
    float cp = 0.f;
    if (t > 0) {
        const float* hr = hh + (size_t)i * BANK4q;
        gi += hr[j]; gf += hr[BANKq + j]; gg += hr[2 * BANKq + j]; go += hr[3 * BANKq + j];
        cp = c[(size_t)i * BANKq + j];
    }
    float cn = sigmoidf_(gf) * cp + sigmoidf_(gi) * tanhf(gg);
    float hn = sigmoidf_(go) * tanhf(cn);
    c[(size_t)i * BANKq + j] = cn;
    hs[((size_t)i * Lq + t) * BANKq + j] = hn;
    bf16 h, l; split1(hn, h, l);
    h_hi[(size_t)i * BANKq + j] = h;
    h_lo[(size_t)i * BANKq + j] = l;
}

__global__ void maxpool_kernel(const float* __restrict__ hs, const int* __restrict__ lens,
                               float* __restrict__ pe)
{
    int i = blockIdx.y;
    int j = blockIdx.x * blockDim.x + threadIdx.x;
    if (j >= BANKq) return;
    int len = lens[i];
    float m = -1e9f;
    const float* base = hs + (size_t)i * Lq * BANKq + j;
    for (int t = 0; t < Lq; t++)
        if (t < len) m = fmaxf(m, base[(size_t)t * BANKq]);
    pe[(size_t)i * BANKq + j] = (len > 0) ? m : 0.f;
}

__global__ void gather_ht_kernel(const float* __restrict__ feats, const int* __restrict__ htp,
                                 float* __restrict__ hf, float* __restrict__ tf,
                                 float* __restrict__ query)
{
    int bp = blockIdx.x;
    int b = bp / Pq;
    int h0 = htp[bp * 2 + 0], t0 = htp[bp * 2 + 1];
    h0 = (h0 == 0) ? 0 : h0 - 1;
    t0 = (t0 == 0) ? 0 : t0 - 1;
    const float* hs = feats + ((size_t)b * Nq + (Nq - Eq) + h0) * BANKq;
    const float* ts = feats + ((size_t)b * Nq + (Nq - Eq) + t0) * BANKq;
    for (int j = threadIdx.x; j < BANKq; j += blockDim.x) {
        float hv = hs[j], tv = ts[j];
        hf[(size_t)bp * BANKq + j] = hv;
        tf[(size_t)bp * BANKq + j] = tv;
        query[(size_t)bp * BANKq + j] = hv - tv;
    }
}

__global__ void mha_attn_kernel(const float* __restrict__ q, const float* __restrict__ k,
                                const float* __restrict__ v, const int* __restrict__ plens,
                                const float* __restrict__ rmask,
                                float* __restrict__ ctx, int* __restrict__ validany)
{
    int bp = blockIdx.x;
    int tid = threadIdx.x;
    int warp = tid >> 5, lane = tid & 31;
    __shared__ float sc[NHq][Kq];
    __shared__ float aw[NHq][Kq];
    __shared__ int vm[Kq];
    if (tid < Kq) vm[tid] = (rmask[bp] > 0.f && plens[bp * Kq + tid] > 0) ? 1 : 0;
    __syncthreads();
    {
        int h = warp / Kq, kk = warp % Kq;
        const float* qh = q + (size_t)bp * BANKq + h * DHq;
        const float* kh = k + ((size_t)bp * Kq + kk) * BANKq + h * DHq;
        float s = 0.f;
        for (int d = lane; d < DHq; d += 32) s += qh[d] * kh[d];
#pragma unroll
        for (int o = 16; o > 0; o >>= 1) s += __shfl_xor_sync(0xffffffffu, s, o);
        if (lane == 0) {
            s = s / sqrtf((float)DHq);
            sc[h][kk] = vm[kk] ? s : -1e9f;
        }
    }
    __syncthreads();
    if (tid < NHq) {
        int h = tid;
        float m = fmaxf(fmaxf(sc[h][0], sc[h][1]), sc[h][2]);
        float e0 = expf(sc[h][0] - m), e1 = expf(sc[h][1] - m), e2 = expf(sc[h][2] - m);
        float s = e0 + e1 + e2;
        aw[h][0] = e0 / s; aw[h][1] = e1 / s; aw[h][2] = e2 / s;
    }
    if (tid == 0) validany[bp] = (vm[0] | vm[1] | vm[2]);
    __syncthreads();
    for (int j = tid; j < BANKq; j += blockDim.x) {
        int h = j / DHq;
        const float* vb = v + (size_t)bp * Kq * BANKq + j;
        float r = aw[h][0] * vb[0] + aw[h][1] * vb[BANKq] + aw[h][2] * vb[2 * BANKq];
        ctx[(size_t)bp * BANKq + j] = r;
    }
}

__global__ void build_of_kernel(const float* __restrict__ hf, const float* __restrict__ tf,
                                const float* __restrict__ pinfo, const int* __restrict__ validany,
                                float* __restrict__ of)
{
    int bp = blockIdx.x;
    int va = validany[bp];
    const float* hr = hf + (size_t)bp * BANKq;
    const float* tr = tf + (size_t)bp * BANKq;
    const float* pr = pinfo + (size_t)bp * BANKq;
    float* o = of + (size_t)bp * BANK5q;
    for (int j = threadIdx.x; j < BANK5q; j += blockDim.x) {
        int seg = j / BANKq, jj = j - seg * BANKq;
        float v;
        if (seg == 0)      v = hr[jj];
        else if (seg == 1) v = tr[jj];
        else if (seg == 2) v = fabsf(hr[jj] - tr[jj]);
        else if (seg == 3) v = hr[jj] * tr[jj];
        else               v = va ? pr[jj] : 0.f;
        o[j] = v;
    }
}

// ---------------- orchestration ----------------
extern "C" void kernel_launch(void* const* d_in, const int* in_sizes, int n_in,
                              void* d_out, int out_size)
{
    const float* encoder_outputs = (const float*)d_in[0];
    const int*   entity_type     = (const int*)  d_in[1];
    const int*   entity_id       = (const int*)  d_in[2];
    const float* sub2words       = (const float*)d_in[3];
    const float* adj             = (const float*)d_in[4];
    const int*   h_t_pairs       = (const int*)  d_in[5];
    const float* rel_mask        = (const float*)d_in[6];
    const int*   path_nodes      = (const int*)  d_in[7];
    const int*   path_lens       = (const int*)  d_in[8];
    const float* type_emb        = (const float*)d_in[9];
    const float* id_emb          = (const float*)d_in[10];
    const float* gcn0_W          = (const float*)d_in[11];
    const float* gcn0_b          = (const float*)d_in[12];
    const float* gcn_W           = (const float*)d_in[13];
    const float* gcn_b           = (const float*)d_in[14];
    const float* attn_Wq         = (const float*)d_in[15];
    const float* attn_Wk         = (const float*)d_in[16];
    const float* attn_Wv         = (const float*)d_in[17];
    const float* lstm_Wih        = (const float*)d_in[18];
    const float* lstm_Whh        = (const float*)d_in[19];
    const float* lstm_b          = (const float*)d_in[20];
    const float* mha_inW         = (const float*)d_in[21];
    const float* mha_inb         = (const float*)d_in[22];
    const float* mha_outW        = (const float*)d_in[23];
    const float* mha_outb        = (const float*)d_in[24];
    const float* pred_W          = (const float*)d_in[25];
    const float* pred_b          = (const float*)d_in[26];
    const float* mW              = (const float*)d_in[27];
    const float* mb              = (const float*)d_in[28];
    const float* bW              = (const float*)d_in[29];
    const float* bb              = (const float*)d_in[30];
    float* out = (float*)d_out;

    void* p;
#define SYMF(var, sym) cudaGetSymbolAddress(&p, sym); float* var = (float*)p;
#define SYMB(var, sym) cudaGetSymbolAddress(&p, sym); bf16* var = (bf16*)p;
    SYMF(enc,   g_enc);    SYMF(feats, g_feats);  SYMF(tmp,   g_tmp);
    SYMF(x1,    g_x1);     SYMF(xq,    g_xq);     SYMF(xk,    g_xk);
    SYMF(xv,    g_xv);     SYMF(att,   g_att);
    SYMF(ih,    g_ih);     SYMF(hh,    g_hh);
    SYMF(cbuf,  g_c);      SYMF(hs0,   g_hs0);    SYMF(hs1,   g_hs1);
    SYMF(pe,    g_pe);     SYMF(hf,    g_hf);     SYMF(tf,    g_tf);
    SYMF(query, g_query);  SYMF(qb,    g_q);      SYMF(kb,    g_k);
    SYMF(vb,    g_v);      SYMF(ctx,   g_ctx);    SYMF(pinfo, g_pinfo);
    SYMF(of,    g_of);     SYMF(hid,   g_hid);
    SYMB(ah,  g_ah);  SYMB(al,  g_al);
    SYMB(sh,  g_sh);  SYMB(sl,  g_sl);
    SYMB(w1h, g_w1h); SYMB(w1l, g_w1l);
    SYMB(w2h, g_w2h); SYMB(w2l, g_w2l);
    SYMB(wph, g_wph); SYMB(wpl, g_wpl);
    cudaGetSymbolAddress(&p, g_validany); int* validany = (int*)p;
#undef SYMF
#undef SYMB

    // 1) enc = concat(encoder_outputs, type_emb[...], id_emb[...])
    build_enc_kernel<<<Bq * Sq, 256>>>(encoder_outputs, entity_type, entity_id, type_emb, id_emb, enc);

    // 2) x0 = sub2words @ enc -> feats[:, :, 0:808]
    gemm(false, sub2words, enc, nullptr, nullptr, feats,
         Nq, D0q, Sq, Sq, D0q, BANKq, 0,
         (long)Nq * Sq, (long)Sq * D0q, (long)Nq * BANKq, 0, Bq, 1.f, 0);

    // 3) tmp = adj @ x0
    gemm(false, adj, feats, nullptr, nullptr, tmp,
         Nq, D0q, Nq, Nq, BANKq, D0q, 0,
         (long)Nq * Nq, (long)Nq * BANKq, (long)Nq * D0q, 0, Bq, 1.f, 0);

    // 4) xg0 = tmp @ gcn0_W + gcn0_b -> feats[:, :, 808:1064]
    gemm(false, tmp, gcn0_W, gcn0_b, nullptr, feats + 808,
         Nq, Gq, D0q, D0q, Gq, BANKq, 0,
         (long)Nq * D0q, 0, (long)Nq * BANKq, 0, Bq, 1.f, 0);

    // 5) GCN + graph-attention layers
    int xoff[NLq]   = {808, 1064};
    int outoff[NLq] = {1064, 1320};
    for (int l = 0; l < NLq; l++) {
        const float* x = feats + xoff[l];
        gemm(false, adj, x, nullptr, nullptr, tmp,
             Nq, Gq, Nq, Nq, BANKq, Gq, 0,
             (long)Nq * Nq, (long)Nq * BANKq, (long)Nq * Gq, 0, Bq, 1.f, 0);
        gemm(false, tmp, gcn_W + (long)l * Gq * Gq, gcn_b + l * Gq, nullptr, x1,
             Nq, Gq, Gq, Gq, Gq, Gq, 0,
             (long)Nq * Gq, 0, (long)Nq * Gq, 0, Bq, 1.f, 1);
        gemm(false, x, attn_Wq + (long)l * Gq * Gq, nullptr, nullptr, xq,
             Nq, Gq, Gq, BANKq, Gq, Gq, 0,
             (long)Nq * BANKq, 0, (long)Nq * Gq, 0, Bq, 1.f, 0);
        gemm(false, x1, attn_Wk + (long)l * Gq * Gq, nullptr, nullptr, xk,
             Nq, Gq, Gq, Gq, Gq, Gq, 0,
             (long)Nq * Gq, 0, (long)Nq * Gq, 0, Bq, 1.f, 0);
        gemm(false, x1, attn_Wv + (long)l * Gq * Gq, nullptr, nullptr, xv,
             Nq, Gq, Gq, Gq, Gq, Gq, 0,
             (long)Nq * Gq, 0, (long)Nq * Gq, 0, Bq, 1.f, 0);
        gemm(true, xq, xk, nullptr, nullptr, att,
             Nq, Nq, Gq, Gq, Gq, Nq, 0,
             (long)Nq * Gq, (long)Nq * Gq, (long)Nq * Nq, 0, Bq, 0.0625f, 0);
        softmax256_kernel<<<Bq * Nq, 256>>>(att);
        gemm(false, att, xv, nullptr, x1, feats + outoff[l],
             Nq, Gq, Nq, Nq, Gq, BANKq, Gq,
             (long)Nq * Nq, (long)Nq * Gq, (long)Nq * BANKq, (long)Nq * Gq, Bq, 1.f, 1);
    }

    // early: pred weight transpose-split (independent of everything above)
    {
        dim3 grid((BANK5q + 31) / 32, (BANK5q + 31) / 32);
        transpose_split_kernel<<<grid, dim3(32, 8)>>>(pred_W, wph, wpl, BANK5q, BANK5q);
    }

    // 6) gather paths -> split bf16
    gather_pf_split_kernel<<<MlstmT, 256>>>(feats, path_nodes, ah, al);

    // 7) two LSTM layers (tensor cores)
    float* hsbuf[2] = {hs0, hs1};
    for (int layer = 0; layer < 2; layer++) {
        const float* Wih = lstm_Wih + (size_t)layer * BANK4q * BANKq;
        const float* Whh = lstm_Whh + (size_t)layer * BANK4q * BANKq;
        const float* bL  = lstm_b + (size_t)layer * BANK4q;
        split(Wih, w1h, w1l, (size_t)BANK4q * BANKq);
        split(Whh, w2h, w2l, (size_t)BANK4q * BANKq);
        if (layer == 1)
            split(hs0, ah, al, (size_t)MlstmT * BANKq);
        gemm_bf16(ah, al, w1h, w1l, bL, ih, MlstmT, BANK4q, BANKq, 0);
        for (int t = 0; t < Lq; t++) {
            if (t > 0)
                gemm_bf16(sh, sl, w2h, w2l, nullptr, hh, Mlstm, BANK4q, BANKq, 0);
            dim3 grid((BANKq + 255) / 256, Mlstm);
            lstm_cell_kernel<<<grid, 256>>>(ih, hh, sh, sl, cbuf, hsbuf[layer], t);
        }
    }

    // 8) masked max-pool over time
    {
        dim3 grid((BANKq + 255) / 256, Mlstm);
        maxpool_kernel<<<grid, 256>>>(hs1, path_lens, pe);
    }

    // 9) h_f, t_f, query
    gather_ht_kernel<<<BPq, 256>>>(feats, h_t_pairs, hf, tf, query);

    // 10-11) q/k/v projections (tensor cores)
    split(mha_inW, w1h, w1l, (size_t)3 * BANKq * BANKq);
    split(query, sh, sl, (size_t)BPq * BANKq);
    gemm_bf16(sh, sl, w1h, w1l, mha_inb, qb, BPq, BANKq, BANKq, 0);
    split(pe, ah, al, (size_t)Mlstm * BANKq);
    gemm_bf16(ah, al, w1h + (size_t)BANKq * BANKq, w1l + (size_t)BANKq * BANKq,
              mha_inb + BANKq, kb, Mlstm, BANKq, BANKq, 0);
    gemm_bf16(ah, al, w1h + 2 * (size_t)BANKq * BANKq, w1l + 2 * (size_t)BANKq * BANKq,
              mha_inb + 2 * BANKq, vb, Mlstm, BANKq, BANKq, 0);

    // 12) tiny attention over K=3 paths
    mha_attn_kernel<<<BPq, 384>>>(qb, kb, vb, path_lens, rel_mask, ctx, validany);

    // 13) pinfo = ctx @ mha_outW^T + mha_outb
    split(mha_outW, w2h, w2l, (size_t)BANKq * BANKq);
    split(ctx, sh, sl, (size_t)BPq * BANKq);
    gemm_bf16(sh, sl, w2h, w2l, mha_outb, pinfo, BPq, BANKq, BANKq, 0);

    // 14) of = [h_f, t_f, |h_f - t_f|, h_f*t_f, pinfo_masked]
    build_of_kernel<<<BPq, 256>>>(hf, tf, pinfo, validany, of);

    // 15) hid = relu(of @ pred_W + pred_b)  (tensor cores)
    split(of, ah, al, (size_t)BPq * BANK5q);
    gemm_bf16(ah, al, wph, wpl, pred_b, hid, BPq, BANK5q, BANK5q, 1);

    // 16) outputs (small N, fp32)
    gemm(false, hid, mW, mb, nullptr, out,
         BPq, Rq, BANK5q, BANK5q, Rq, Rq, 0, 0, 0, 0, 0, 1, 1.f, 0);
    gemm(false, hid, bW, bb, nullptr, out + (size_t)BPq * Rq,
         BPq, 2, BANK5q, BANK5q, 2, 2, 0, 0, 0, 0, 0, 1, 1.f, 0);
}

// round 3
// speedup vs baseline: 1.8387x; 1.1351x over previous
#include <cuda_runtime.h>
#include <cuda_bf16.h>
#include <math.h>
#include <stdio.h>

// ---------------- problem constants ----------------
#define Bq   4
#define Sq   512
#define Nq   256
#define Eq   42
#define Pq   256
#define Kq   3
#define Lq   4
#define HBq  768
#define DTq  20
#define DIq  20
#define Gq   256
#define NLq  2
#define Rq   97
#define NHq  4
#define D0q  808          // HB+DT+DI
#define BANKq 1576        // D0 + G*(NL+1)
#define BANK4q 6304       // 4*BANK
#define BANK5q 7880       // 5*BANK
#define DHq  394          // BANK/NH
#define Mlstm (Bq*Pq*Kq)        // 3072
#define MlstmT (Mlstm*Lq)       // 12288
#define BPq  (Bq*Pq)            // 1024

typedef __nv_bfloat16 bf16;
typedef __nv_bfloat162 bf162;

// ---------------- scratch (static device memory; no allocations allowed) ----------------
__device__ float g_enc   [Bq*Sq*D0q];
__device__ float g_feats [Bq*Nq*BANKq];
__device__ float g_tmp   [Bq*Nq*D0q];
__device__ float g_x1    [Bq*Nq*Gq];
__device__ float g_xq    [Bq*Nq*Gq];
__device__ float g_xk    [Bq*Nq*Gq];
__device__ float g_xv    [Bq*Nq*Gq];
__device__ float g_att   [Bq*Nq*Nq];
__device__ float g_ih    [(size_t)MlstmT*BANK4q];
__device__ float g_hh    [(size_t)Mlstm*BANK4q];
__device__ float g_c     [Mlstm*BANKq];
__device__ float g_hs1   [MlstmT*BANKq];
__device__ float g_hf    [BPq*BANKq];
__device__ float g_tf    [BPq*BANKq];
__device__ float g_q     [BPq*BANKq];
__device__ float g_k     [Mlstm*BANKq];
__device__ float g_v     [Mlstm*BANKq];
__device__ float g_pinfo [BPq*BANKq];
__device__ int   g_validany[BPq];
__device__ float g_hid   [BPq*BANK5q];

// bf16 split scratch
__device__ bf16 g_ah  [(size_t)MlstmT*BANKq];     // big activations hi
__device__ bf16 g_al  [(size_t)MlstmT*BANKq];     // big activations lo
__device__ bf16 g_sh  [(size_t)Mlstm*BANKq];      // small activations hi
__device__ bf16 g_sl  [(size_t)Mlstm*BANKq];
__device__ bf16 g_w1h [(size_t)BANK4q*BANKq];
__device__ bf16 g_w1l [(size_t)BANK4q*BANKq];
__device__ bf16 g_w2h [(size_t)BANK4q*BANKq];
__device__ bf16 g_w2l [(size_t)BANK4q*BANKq];
__device__ bf16 g_wph [(size_t)BANK5q*BANK5q];    // pred weight transposed
__device__ bf16 g_wpl [(size_t)BANK5q*BANK5q];

// ================= fp32 tiled GEMMs (for small GCN ops) =================
#define TS 128
#define KS 8

template <bool TRANSB>
__global__ void __launch_bounds__(256, 2)
gemm_kernel(const float* __restrict__ A, const float* __restrict__ B,
            const float* __restrict__ bias, const float* __restrict__ resid,
            float* __restrict__ C,
            int M, int N, int K,
            int lda, int ldb, int ldc, int ldr,
            long sA, long sB, long sC, long sR,
            float alpha, int act)
{
    int bz = blockIdx.z;
    A += bz * sA; B += bz * sB; C += bz * sC;
    if (resid) resid += bz * sR;

    int row0 = blockIdx.y * TS;
    int col0 = blockIdx.x * TS;

    __shared__ float As[KS][TS];
    __shared__ float Bs[KS][TS + 4];

    int tid = threadIdx.x;
    int tx = tid & 15, ty = tid >> 4;

    float acc[8][8];
#pragma unroll
    for (int i = 0; i < 8; i++)
#pragma unroll
        for (int j = 0; j < 8; j++) acc[i][j] = 0.f;

    for (int k0 = 0; k0 < K; k0 += KS) {
#pragma unroll
        for (int l = 0; l < 4; l++) {
            int idx = tid + l * 256;
            int m = idx >> 3, kk = idx & 7;
            int gr = row0 + m, gk = k0 + kk;
            As[kk][m] = (gr < M && gk < K) ? A[(long)gr * lda + gk] : 0.f;
        }
#pragma unroll
        for (int l = 0; l < 4; l++) {
            int idx = tid + l * 256;
            if (TRANSB) {
                int n = idx >> 3, kk = idx & 7;
                int gn = col0 + n, gk = k0 + kk;
                Bs[kk][n] = (gn < N && gk < K) ? B[(long)gn * ldb + gk] : 0.f;
            } else {
                int kk = idx >> 7, n = idx & 127;
                int gn = col0 + n, gk = k0 + kk;
                Bs[kk][n] = (gn < N && gk < K) ? B[(long)gk * ldb + gn] : 0.f;
            }
        }
        __syncthreads();
#pragma unroll
        for (int kk = 0; kk < KS; kk++) {
            float a[8], b[8];
#pragma unroll
            for (int i = 0; i < 8; i++) a[i] = As[kk][ty + 16 * i];
#pragma unroll
            for (int j = 0; j < 8; j++) b[j] = Bs[kk][tx + 16 * j];
#pragma unroll
            for (int i = 0; i < 8; i++)
#pragma unroll
                for (int j = 0; j < 8; j++)
                    acc[i][j] = fmaf(a[i], b[j], acc[i][j]);
        }
        __syncthreads();
    }

#pragma unroll
    for (int i = 0; i < 8; i++) {
        int r = row0 + ty + 16 * i;
        if (r >= M) continue;
#pragma unroll
        for (int j = 0; j < 8; j++) {
            int cc = col0 + tx + 16 * j;
            if (cc >= N) continue;
            float v = acc[i][j] * alpha;
            if (bias) v += bias[cc];
            if (act == 1) v = fmaxf(v, 0.f);
            if (resid) v += resid[(long)r * ldr + cc];
            C[(long)r * ldc + cc] = v;
        }
    }
}

template <bool TRANSB>
__global__ void __launch_bounds__(256)
gemm64_kernel(const float* __restrict__ A, const float* __restrict__ B,
              const float* __restrict__ bias, const float* __restrict__ resid,
              float* __restrict__ C,
              int M, int N, int K,
              int lda, int ldb, int ldc, int ldr,
              long sA, long sB, long sC, long sR,
              float alpha, int act)
{
    int bz = blockIdx.z;
    A += bz * sA; B += bz * sB; C += bz * sC;
    if (resid) resid += bz * sR;

    int row0 = blockIdx.y * 64;
    int col0 = blockIdx.x * 64;

    __shared__ float As[16][64 + 1];
    __shared__ float Bs[16][64 + 1];

    int tid = threadIdx.x;
    int tx = tid & 15, ty = tid >> 4;

    float acc[4][4];
#pragma unroll
    for (int i = 0; i < 4; i++)
#pragma unroll
        for (int j = 0; j < 4; j++) acc[i][j] = 0.f;

    for (int k0 = 0; k0 < K; k0 += 16) {
#pragma unroll
        for (int l = 0; l < 4; l++) {
            int idx = tid + l * 256;
            int m = idx >> 4, kk = idx & 15;
            int gr = row0 + m, gk = k0 + kk;
            As[kk][m] = (gr < M && gk < K) ? A[(long)gr * lda + gk] : 0.f;
        }
#pragma unroll
        for (int l = 0; l < 4; l++) {
            int idx = tid + l * 256;
            if (TRANSB) {
                int n = idx >> 4, kk = idx & 15;
                int gn = col0 + n, gk = k0 + kk;
                Bs[kk][n] = (gn < N && gk < K) ? B[(long)gn * ldb + gk] : 0.f;
            } else {
                int kk = idx >> 6, n = idx & 63;
                int gn = col0 + n, gk = k0 + kk;
                Bs[kk][n] = (gn < N && gk < K) ? B[(long)gk * ldb + gn] : 0.f;
            }
        }
        __syncthreads();
#pragma unroll
        for (int kk = 0; kk < 16; kk++) {
            float a[4], b[4];
#pragma unroll
            for (int i = 0; i < 4; i++) a[i] = As[kk][ty + 16 * i];
#pragma unroll
            for (int j = 0; j < 4; j++) b[j] = Bs[kk][tx + 16 * j];
#pragma unroll
            for (int i = 0; i < 4; i++)
#pragma unroll
                for (int j = 0; j < 4; j++)
                    acc[i][j] = fmaf(a[i], b[j], acc[i][j]);
        }
        __syncthreads();
    }

#pragma unroll
    for (int i = 0; i < 4; i++) {
        int r = row0 + ty + 16 * i;
        if (r >= M) continue;
#pragma unroll
        for (int j = 0; j < 4; j++) {
            int cc = col0 + tx + 16 * j;
            if (cc >= N) continue;
            float v = acc[i][j] * alpha;
            if (bias) v += bias[cc];
            if (act == 1) v = fmaxf(v, 0.f);
            if (resid) v += resid[(long)r * ldr + cc];
            C[(long)r * ldc + cc] = v;
        }
    }
}

static void gemm(bool transB,
                 const float* A, const float* B, const float* bias, const float* resid, float* C,
                 int M, int N, int K, int lda, int ldb, int ldc, int ldr,
                 long sA, long sB, long sC, long sR, int batch, float alpha, int act)
{
    if (M <= 256) {
        dim3 grid((N + 63) / 64, (M + 63) / 64, batch);
        if (transB)
            gemm64_kernel<true><<<grid, 256>>>(A, B, bias, resid, C, M, N, K, lda, ldb, ldc, ldr, sA, sB, sC, sR, alpha, act);
        else
            gemm64_kernel<false><<<grid, 256>>>(A, B, bias, resid, C, M, N, K, lda, ldb, ldc, ldr, sA, sB, sC, sR, alpha, act);
    } else {
        dim3 grid((N + TS - 1) / TS, (M + TS - 1) / TS, batch);
        if (transB)
            gemm_kernel<true><<<grid, 256>>>(A, B, bias, resid, C, M, N, K, lda, ldb, ldc, ldr, sA, sB, sC, sR, alpha, act);
        else
            gemm_kernel<false><<<grid, 256>>>(A, B, bias, resid, C, M, N, K, lda, ldb, ldc, ldr, sA, sB, sC, sR, alpha, act);
    }
}

// ================= bf16 split-precision tensor-core GEMM (pipelined) =================
// C(MxN) = A(MxK) @ B(NxK)^T + bias, A = Ah+Al, B = Bh+Bl.
// acc += Ah*Bh + Ah*Bl + Al*Bh
#define LDSB 40                    // padded row stride in bf16 (80B -> conflict-free ldmatrix)
#define GSTG 3                     // pipeline stages
#define PLANE_E (128*LDSB)         // elems per plane
#define PLANE_B (PLANE_E*2)        // bytes per plane (10240)
#define STAGE_B (4*PLANE_B)        // bytes per stage  (40960)

#define MMA_BF16(d, a, b) asm volatile( \
    "mma.sync.aligned.m16n8k16.row.col.f32.bf16.bf16.f32 " \
    "{%0,%1,%2,%3}, {%4,%5,%6,%7}, {%8,%9}, {%0,%1,%2,%3};" \
    : "+f"((d)[0]), "+f"((d)[1]), "+f"((d)[2]), "+f"((d)[3]) \
    : "r"((a)[0]), "r"((a)[1]), "r"((a)[2]), "r"((a)[3]), "r"((b)[0]), "r"((b)[1]))

#define LDSM4(r, addr) asm volatile( \
    "ldmatrix.sync.aligned.m8n8.x4.shared.b16 {%0,%1,%2,%3}, [%4];" \
    : "=r"((r)[0]), "=r"((r)[1]), "=r"((r)[2]), "=r"((r)[3]) : "r"(addr))

__device__ __forceinline__ void cpasync16(unsigned saddr, const void* g, int srcbytes)
{
    asm volatile("cp.async.cg.shared.global [%0], [%1], 16, %2;\n"
                 :: "r"(saddr), "l"(g), "r"(srcbytes));
}

__device__ __forceinline__ void gbf_prefetch(
    const bf16* __restrict__ Ah, const bf16* __restrict__ Al,
    const bf16* __restrict__ Bh, const bf16* __restrict__ Bl,
    long row0, long col0, int M, int N, int K,
    int kt, int T, unsigned sbase, int stg, int tid)
{
    if (kt >= T) return;
    long k0 = (long)kt * 32;
    unsigned sst = sbase + (unsigned)stg * STAGE_B;
#pragma unroll
    for (int i = 0; i < 2; i++) {
        int c = tid + i * 256;          // 512 chunks of 16B per plane
        int r = c >> 2;
        int ko = (c & 3) * 8;
        long gk = k0 + ko;
        bool kok = gk < K;
        long gkc = kok ? gk : 0;
        unsigned soff = (unsigned)((r * LDSB + ko) * 2);
        {
            long gr = row0 + r;
            bool ok = kok && (gr < M);
            long grc = ok ? gr : 0;
            int nb = ok ? 16 : 0;
            cpasync16(sst + soff,            Ah + grc * K + gkc, nb);
            cpasync16(sst + PLANE_B + soff,  Al + grc * K + gkc, nb);
        }
        {
            long gn = col0 + r;
            bool ok = kok && (gn < N);
            long gnc = ok ? gn : 0;
            int nb = ok ? 16 : 0;
            cpasync16(sst + 2 * PLANE_B + soff, Bh + gnc * K + gkc, nb);
            cpasync16(sst + 3 * PLANE_B + soff, Bl + gnc * K + gkc, nb);
        }
    }
}

__global__ void __launch_bounds__(256)
gemm_bf16_kernel(const bf16* __restrict__ Ah, const bf16* __restrict__ Al,
                 const bf16* __restrict__ Bh, const bf16* __restrict__ Bl,
                 const float* __restrict__ bias, float* __restrict__ C,
                 int M, int N, int K, int act)
{
    extern __shared__ __align__(16) bf16 dsm[];
    unsigned sbase = (unsigned)__cvta_generic_to_shared(dsm);

    int tid = threadIdx.x;
    int warp = tid >> 5, lane = tid & 31;
    int wm = (warp & 1) * 64;
    int wn = (warp >> 1) * 32;
    long row0 = (long)blockIdx.y * 128;
    long col0 = (long)blockIdx.x * 128;

    float acc[4][4][4];
#pragma unroll
    for (int a = 0; a < 4; a++)
#pragma unroll
        for (int b = 0; b < 4; b++)
#pragma unroll
            for (int c = 0; c < 4; c++) acc[a][b][c] = 0.f;

    int am_r = (lane & 7) + ((lane >> 3) & 1) * 8;
    int a_c8 = ((lane >> 4) & 1) * 8;
    int b_r  = (lane & 7) + ((lane >> 4) & 1) * 8;
    int b_c8 = ((lane >> 3) & 1) * 8;

    int T = (K + 31) / 32;   // always >= GSTG for our shapes

    // prologue: fill the pipeline
#pragma unroll
    for (int kt = 0; kt < GSTG; kt++) {
        gbf_prefetch(Ah, Al, Bh, Bl, row0, col0, M, N, K, kt, T, sbase, kt, tid);
        asm volatile("cp.async.commit_group;\n");
    }

    for (int kt = 0; kt < T; kt++) {
        asm volatile("cp.async.wait_group %0;\n" :: "n"(GSTG - 1));
        __syncthreads();

        int stg = kt % GSTG;
        unsigned sst = sbase + (unsigned)stg * STAGE_B;
        unsigned aB = sst;
        unsigned bB = sst + 2 * PLANE_B;

#pragma unroll
        for (int ks = 0; ks < 2; ks++) {
            int kb = ks * 16;
            unsigned bh[2][4], bl[2][4];
#pragma unroll
            for (int pp = 0; pp < 2; pp++) {
                unsigned addr = bB + (unsigned)(((wn + pp * 16 + b_r) * LDSB + kb + b_c8) * 2);
                LDSM4(bh[pp], addr);
                LDSM4(bl[pp], addr + PLANE_B);
            }
#pragma unroll
            for (int mi = 0; mi < 4; mi++) {
                unsigned ahf[4], alf[4];
                unsigned addr = aB + (unsigned)(((wm + mi * 16 + am_r) * LDSB + kb + a_c8) * 2);
                LDSM4(ahf, addr);
                LDSM4(alf, addr + PLANE_B);
#pragma unroll
                for (int ni = 0; ni < 4; ni++) {
                    unsigned* ph = &bh[ni >> 1][(ni & 1) * 2];
                    unsigned* pl = &bl[ni >> 1][(ni & 1) * 2];
                    MMA_BF16(acc[mi][ni], ahf, ph);
                    MMA_BF16(acc[mi][ni], ahf, pl);
                    MMA_BF16(acc[mi][ni], alf, ph);
                }
            }
        }
        __syncthreads();
        gbf_prefetch(Ah, Al, Bh, Bl, row0, col0, M, N, K, kt + GSTG, T, sbase, stg, tid);
        asm volatile("cp.async.commit_group;\n");
    }

    // ---- epilogue ----
#pragma unroll
    for (int mi = 0; mi < 4; mi++) {
#pragma unroll
        for (int ni = 0; ni < 4; ni++) {
            long r = row0 + wm + mi * 16 + (lane >> 2);
            long c = col0 + wn + ni * 8 + (lane & 3) * 2;
#pragma unroll
            for (int half = 0; half < 2; half++) {
                long rr = r + half * 8;
                if (rr >= M) continue;
#pragma unroll
                for (int e = 0; e < 2; e++) {
                    long cc = c + e;
                    if (cc >= N) continue;
                    float v = acc[mi][ni][half * 2 + e];
                    if (bias) v += bias[cc];
                    if (act == 1) v = fmaxf(v, 0.f);
                    C[(size_t)rr * N + cc] = v;
                }
            }
        }
    }
}

static void gemm_bf16(const bf16* Ah, const bf16* Al, const bf16* Bh, const bf16* Bl,
                      const float* bias, float* C, int M, int N, int K, int act)
{
    static int attr_done = 0;
    if (!attr_done) {
        cudaFuncSetAttribute(gemm_bf16_kernel,
                             cudaFuncAttributeMaxDynamicSharedMemorySize, GSTG * STAGE_B);
        attr_done = 1;
    }
    dim3 grid((N + 127) / 128, (M + 127) / 128);
    gemm_bf16_kernel<<<grid, 256, GSTG * STAGE_B>>>(Ah, Al, Bh, Bl, bias, C, M, N, K, act);
}

// ================= conversion kernels =================
__device__ __forceinline__ void split1(float f, bf16& h, bf16& l)
{
    h = __float2bfloat16(f);
    l = __float2bfloat16(f - __bfloat162float(h));
}

__global__ void split_kernel(const float* __restrict__ x, bf16* __restrict__ hi,
                             bf16* __restrict__ lo, size_t n4)
{
    size_t i = (size_t)blockIdx.x * blockDim.x + threadIdx.x;
    if (i >= n4) return;
    float4 f = ((const float4*)x)[i];
    bf16 h0, l0, h1, l1, h2, l2, h3, l3;
    split1(f.x, h0, l0); split1(f.y, h1, l1); split1(f.z, h2, l2); split1(f.w, h3, l3);
    bf162 vh0; vh0.x = h0; vh0.y = h1;
    bf162 vh1; vh1.x = h2; vh1.y = h3;
    bf162 vl0; vl0.x = l0; vl0.y = l1;
    bf162 vl1; vl1.x = l2; vl1.y = l3;
    ((bf162*)hi)[i * 2] = vh0; ((bf162*)hi)[i * 2 + 1] = vh1;
    ((bf162*)lo)[i * 2] = vl0; ((bf162*)lo)[i * 2 + 1] = vl1;
}

static void split(const float* x, bf16* hi, bf16* lo, size_t n)
{
    size_t n4 = n / 4;
    split_kernel<<<(unsigned)((n4 + 255) / 256), 256>>>(x, hi, lo, n4);
}

// transpose + split: B (KxN fp32) -> Th/Tl ([N][K] bf16)
__global__ void transpose_split_kernel(const float* __restrict__ B, bf16* __restrict__ Th,
                                       bf16* __restrict__ Tl, int K, int N)
{
    __shared__ float tile[32][33];
    int k0 = blockIdx.y * 32, n0 = blockIdx.x * 32;
    int tx = threadIdx.x, ty = threadIdx.y;  // 32 x 8
#pragma unroll
    for (int i = 0; i < 32; i += 8) {
        int k = k0 + ty + i, n = n0 + tx;
        tile[ty + i][tx] = (k < K && n < N) ? B[(size_t)k * N + n] : 0.f;
    }
    __syncthreads();
#pragma unroll
    for (int i = 0; i < 32; i += 8) {
        int n = n0 + ty + i, k = k0 + tx;
        if (n < N && k < K) {
            float f = tile[tx][ty + i];
            bf16 h, l; split1(f, h, l);
            Th[(size_t)n * K + k] = h;
            Tl[(size_t)n * K + k] = l;
        }
    }
}

// ---------------- small custom kernels ----------------
__global__ void build_enc_kernel(const float* __restrict__ eo, const int* __restrict__ etype,
                                 const int* __restrict__ eid, const float* __restrict__ temb,
                                 const float* __restrict__ iemb, float* __restrict__ enc)
{
    int bs = blockIdx.x;
    const float* src = eo + (long)bs * HBq;
    float* dst = enc + (long)bs * D0q;
    int ty = etype[bs], idv = eid[bs];
    for (int j = threadIdx.x; j < D0q; j += blockDim.x) {
        float v;
        if (j < HBq)            v = src[j];
        else if (j < HBq + DTq) v = temb[ty * DTq + (j - HBq)];
        else                    v = iemb[idv * DIq + (j - HBq - DTq)];
        dst[j] = v;
    }
}

__global__ void softmax256_kernel(float* __restrict__ x)
{
    int row = blockIdx.x;
    int tid = threadIdx.x;
    float v = x[(long)row * 256 + tid];
    __shared__ float red[8];
    int lane = tid & 31, warp = tid >> 5;
    float m = v;
#pragma unroll
    for (int o = 16; o > 0; o >>= 1) m = fmaxf(m, __shfl_xor_sync(0xffffffffu, m, o));
    if (lane == 0) red[warp] = m;
    __syncthreads();
    if (tid == 0) {
        float mm = red[0];
        for (int w = 1; w < 8; w++) mm = fmaxf(mm, red[w]);
        red[0] = mm;
    }
    __syncthreads();
    float mx = red[0];
    float e = expf(v - mx);
    float s = e;
#pragma unroll
    for (int o = 16; o > 0; o >>= 1) s += __shfl_xor_sync(0xffffffffu, s, o);
    __shared__ float red2[8];
    if (lane == 0) red2[warp] = s;
    __syncthreads();
    if (tid == 0) {
        float ss = 0.f;
        for (int w = 0; w < 8; w++) ss += red2[w];
        red2[0] = ss;
    }
    __syncthreads();
    x[(long)row * 256 + tid] = e / red2[0];
}

__global__ void gather_pf_split_kernel(const float* __restrict__ feats, const int* __restrict__ nodes,
                                       bf16* __restrict__ hi, bf16* __restrict__ lo)
{
    int row = blockIdx.x;                 // 0..12287
    int b = row / (Pq * Kq * Lq);
    int node = nodes[row];
    const float* src = feats + ((size_t)b * Nq + node) * BANKq;
    size_t base = (size_t)row * BANKq;
    for (int j = threadIdx.x; j < BANKq; j += blockDim.x) {
        bf16 h, l; split1(src[j], h, l);
        hi[base + j] = h;
        lo[base + j] = l;
    }
}

__device__ __forceinline__ float sigmoidf_(float x) { return 1.f / (1.f + expf(-x)); }

__global__ void lstm_cell_kernel(const float* __restrict__ ih, const float* __restrict__ hh,
                                 bf16* __restrict__ h_hi, bf16* __restrict__ h_lo,
                                 bf16* __restrict__ seq_hi, bf16* __restrict__ seq_lo,
                                 float* __restrict__ c, float* __restrict__ hs, int t)
{
    int i = blockIdx.y;
    int j = blockIdx.x * blockDim.x + threadIdx.x;
    if (j >= BANKq) return;
    const float* g = ih + ((size_t)i * Lq + t) * BANK4q;
    float gi = g[j], gf = g[BANKq + j], gg = g[2 * BANKq + j], go = g[3 * BANKq + j];
    float cp = 0.f;
    if (t > 0) {
        const float* hr = hh + (size_t)i * BANK4q;
        gi += hr[j]; gf += hr[BANKq + j]; gg += hr[2 * BANKq + j]; go += hr[3 * BANKq + j];
        cp = c[(size_t)i * BANKq + j];
    }
    float cn = sigmoidf_(gf) * cp + sigmoidf_(gi) * tanhf(gg);
    float hn = sigmoidf_(go) * tanhf(cn);
    c[(size_t)i * BANKq + j] = cn;
    bf16 h, l; split1(hn, h, l);
    h_hi[(size_t)i * BANKq + j] = h;
    h_lo[(size_t)i * BANKq + j] = l;
    if (seq_hi) {
        seq_hi[((size_t)i * Lq + t) * BANKq + j] = h;
        seq_lo[((size_t)i * Lq + t) * BANKq + j] = l;
    }
    if (hs) hs[((size_t)i * Lq + t) * BANKq + j] = hn;
}

__global__ void maxpool_split_kernel(const float* __restrict__ hs, const int* __restrict__ lens,
                                     bf16* __restrict__ hi, bf16* __restrict__ lo)
{
    int i = blockIdx.y;
    int j = blockIdx.x * blockDim.x + threadIdx.x;
    if (j >= BANKq) return;
    int len = lens[i];
    float m = -1e9f;
    const float* base = hs + (size_t)i * Lq * BANKq + j;
    for (int t = 0; t < Lq; t++)
        if (t < len) m = fmaxf(m, base[(size_t)t * BANKq]);
    float r = (len > 0) ? m : 0.f;
    bf16 h, l; split1(r, h, l);
    hi[(size_t)i * BANKq + j] = h;
    lo[(size_t)i * BANKq + j] = l;
}

__global__ void gather_ht_kernel(const float* __restrict__ feats, const int* __restrict__ htp,
                                 float* __restrict__ hf, float* __restrict__ tf,
                                 bf16* __restrict__ qh, bf16* __restrict__ ql)
{
    int bp = blockIdx.x;
    int b = bp / Pq;
    int h0 = htp[bp * 2 + 0], t0 = htp[bp * 2 + 1];
    h0 = (h0 == 0) ? 0 : h0 - 1;
    t0 = (t0 == 0) ? 0 : t0 - 1;
    const float* hsrc = feats + ((size_t)b * Nq + (Nq - Eq) + h0) * BANKq;
    const float* tsrc = feats + ((size_t)b * Nq + (Nq - Eq) + t0) * BANKq;
    for (int j = threadIdx.x; j < BANKq; j += blockDim.x) {
        float hv = hsrc[j], tv = tsrc[j];
        hf[(size_t)bp * BANKq + j] = hv;
        tf[(size_t)bp * BANKq + j] = tv;
        bf16 h, l; split1(hv - tv, h, l);
        qh[(size_t)bp * BANKq + j] = h;
        ql[(size_t)bp * BANKq + j] = l;
    }
}

__global__ void mha_attn_kernel(const float* __restrict__ q, const float* __restrict__ k,
                                const float* __restrict__ v, const int* __restrict__ plens,
                                const float* __restrict__ rmask,
                                bf16* __restrict__ ctx_hi, bf16* __restrict__ ctx_lo,
                                int* __restrict__ validany)
{
    int bp = blockIdx.x;
    int tid = threadIdx.x;
    int warp = tid >> 5, lane = tid & 31;
    __shared__ float sc[NHq][Kq];
    __shared__ float aw[NHq][Kq];
    __shared__ int vm[Kq];
    if (tid < Kq) vm[tid] = (rmask[bp] > 0.f && plens[bp * Kq + tid] > 0) ? 1 : 0;
    __syncthreads();
    {
        int h = warp / Kq, kk = warp % Kq;
        const float* qh = q + (size_t)bp * BANKq + h * DHq;
        const float* kh = k + ((size_t)bp * Kq + kk) * BANKq + h * DHq;
        float s = 0.f;
        for (int d = lane; d < DHq; d += 32) s += qh[d] * kh[d];
#pragma unroll
        for (int o = 16; o > 0; o >>= 1) s += __shfl_xor_sync(0xffffffffu, s, o);
        if (lane == 0) {
            s = s / sqrtf((float)DHq);
            sc[h][kk] = vm[kk] ? s : -1e9f;
        }
    }
    __syncthreads();
    if (tid < NHq) {
        int h = tid;
        float m = fmaxf(fmaxf(sc[h][0], sc[h][1]), sc[h][2]);
        float e0 = expf(sc[h][0] - m), e1 = expf(sc[h][1] - m), e2 = expf(sc[h][2] - m);
        float s = e0 + e1 + e2;
        aw[h][0] = e0 / s; aw[h][1] = e1 / s; aw[h][2] = e2 / s;
    }
    if (tid == 0) validany[bp] = (vm[0] | vm[1] | vm[2]);
    __syncthreads();
    for (int j = tid; j < BANKq; j += blockDim.x) {
        int h = j / DHq;
        const float* vb = v + (size_t)bp * Kq * BANKq + j;
        float r = aw[h][0] * vb[0] + aw[h][1] * vb[BANKq] + aw[h][2] * vb[2 * BANKq];
        bf16 hh2, ll2; split1(r, hh2, ll2);
        ctx_hi[(size_t)bp * BANKq + j] = hh2;
        ctx_lo[(size_t)bp * BANKq + j] = ll2;
    }
}

__global__ void build_of_split_kernel(const float* __restrict__ hf, const float* __restrict__ tf,
                                      const float* __restrict__ pinfo, const int* __restrict__ validany,
                                      bf16* __restrict__ oh, bf16* __restrict__ ol)
{
    int bp = blockIdx.x;
    int va = validany[bp];
    const float* hr = hf + (size_t)bp * BANKq;
    const float* tr = tf + (size_t)bp * BANKq;
    const float* pr = pinfo + (size_t)bp * BANKq;
    size_t base = (size_t)bp * BANK5q;
    for (int j = threadIdx.x; j < BANK5q; j += blockDim.x) {
        int seg = j / BANKq, jj = j - seg * BANKq;
        float v;
        if (seg == 0)      v = hr[jj];
        else if (seg == 1) v = tr[jj];
        else if (seg == 2) v = fabsf(hr[jj] - tr[jj]);
        else if (seg == 3) v = hr[jj] * tr[jj];
        else               v = va ? pr[jj] : 0.f;
        bf16 h, l; split1(v, h, l);
        oh[base + j] = h;
        ol[base + j] = l;
    }
}

// fused output heads: out1 = hid@mW+mb (1024x97), out2 = hid@bW+bb (1024x2)
__global__ void __launch_bounds__(256)
head_kernel(const float* __restrict__ hid, const float* __restrict__ mW,
            const float* __restrict__ mb, const float* __restrict__ bW,
            const float* __restrict__ bb, float* __restrict__ out)
{
    int m = blockIdx.x;
    __shared__ float srow[BANK5q];
    __shared__ float part[2][Rq + 2];
    const float* hr = hid + (size_t)m * BANK5q;
    for (int j = threadIdx.x; j < BANK5q; j += 256) srow[j] = hr[j];
    __syncthreads();
    int t = threadIdx.x;
    const int NT = Rq + 2;  // 99
    if (t < 2 * NT) {
        int ks = t / NT, n = t - ks * NT;
        int k0 = ks * (BANK5q / 2), k1 = k0 + BANK5q / 2;
        float acc = 0.f;
        if (n < Rq) {
#pragma unroll 8
            for (int k = k0; k < k1; k++) acc += srow[k] * mW[(size_t)k * Rq + n];
        } else {
            int nb = n - Rq;
#pragma unroll 8
            for (int k = k0; k < k1; k++) acc += srow[k] * bW[(size_t)k * 2 + nb];
        }
        part[ks][n] = acc;
    }
    __syncthreads();
    if (t < NT) {
        float v = part[0][t] + part[1][t];
        if (t < Rq) out[(size_t)m * Rq + t] = v + mb[t];
        else        out[(size_t)BPq * Rq + (size_t)m * 2 + (t - Rq)] = v + bb[t - Rq];
    }
}

// ---------------- orchestration ----------------
extern "C" void kernel_launch(void* const* d_in, const int* in_sizes, int n_in,
                              void* d_out, int out_size)
{
    const float* encoder_outputs = (const float*)d_in[0];
    const int*   entity_type     = (const int*)  d_in[1];
    const int*   entity_id       = (const int*)  d_in[2];
    const float* sub2words       = (const float*)d_in[3];
    const float* adj             = (const float*)d_in[4];
    const int*   h_t_pairs       = (const int*)  d_in[5];
    const float* rel_mask        = (const float*)d_in[6];
    const int*   path_nodes      = (const int*)  d_in[7];
    const int*   path_lens       = (const int*)  d_in[8];
    const float* type_emb        = (const float*)d_in[9];
    const float* id_emb          = (const float*)d_in[10];
    const float* gcn0_W          = (const float*)d_in[11];
    const float* gcn0_b          = (const float*)d_in[12];
    const float* gcn_W           = (const float*)d_in[13];
    const float* gcn_b           = (const float*)d_in[14];
    const float* attn_Wq         = (const float*)d_in[15];
    const float* attn_Wk         = (const float*)d_in[16];
    const float* attn_Wv         = (const float*)d_in[17];
    const float* lstm_Wih        = (const float*)d_in[18];
    const float* lstm_Whh        = (const float*)d_in[19];
    const float* lstm_b          = (const float*)d_in[20];
    const float* mha_inW         = (const float*)d_in[21];
    const float* mha_inb         = (const float*)d_in[22];
    const float* mha_outW        = (const float*)d_in[23];
    const float* mha_outb        = (const float*)d_in[24];
    const float* pred_W          = (const float*)d_in[25];
    const float* pred_b          = (const float*)d_in[26];
    const float* mW              = (const float*)d_in[27];
    const float* mb              = (const float*)d_in[28];
    const float* bW              = (const float*)d_in[29];
    const float* bb              = (const float*)d_in[30];
    float* out = (float*)d_out;

    void* p;
#define SYMF(var, sym) cudaGetSymbolAddress(&p, sym); float* var = (float*)p;
#define SYMB(var, sym) cudaGetSymbolAddress(&p, sym); bf16* var = (bf16*)p;
    SYMF(enc,   g_enc);    SYMF(feats, g_feats);  SYMF(tmp,   g_tmp);
    SYMF(x1,    g_x1);     SYMF(xq,    g_xq);     SYMF(xk,    g_xk);
    SYMF(xv,    g_xv);     SYMF(att,   g_att);
    SYMF(ih,    g_ih);     SYMF(hh,    g_hh);
    SYMF(cbuf,  g_c);      SYMF(hs1,   g_hs1);
    SYMF(hf,    g_hf);     SYMF(tf,    g_tf);
    SYMF(qb,    g_q);      SYMF(kb,    g_k);      SYMF(vb,    g_v);
    SYMF(pinfo, g_pinfo);  SYMF(hid,   g_hid);
    SYMB(ah,  g_ah);  SYMB(al,  g_al);
    SYMB(sh,  g_sh);  SYMB(sl,  g_sl);
    SYMB(w1h, g_w1h); SYMB(w1l, g_w1l);
    SYMB(w2h, g_w2h); SYMB(w2l, g_w2l);
    SYMB(wph, g_wph); SYMB(wpl, g_wpl);
    cudaGetSymbolAddress(&p, g_validany); int* validany = (int*)p;
#undef SYMF
#undef SYMB

    // 1) enc = concat(encoder_outputs, type_emb[...], id_emb[...])
    build_enc_kernel<<<Bq * Sq, 256>>>(encoder_outputs, entity_type, entity_id, type_emb, id_emb, enc);

    // 2) x0 = sub2words @ enc -> feats[:, :, 0:808]
    gemm(false, sub2words, enc, nullptr, nullptr, feats,
         Nq, D0q, Sq, Sq, D0q, BANKq, 0,
         (long)Nq * Sq, (long)Sq * D0q, (long)Nq * BANKq, 0, Bq, 1.f, 0);

    // 3) tmp = adj @ x0
    gemm(false, adj, feats, nullptr, nullptr, tmp,
         Nq, D0q, Nq, Nq, BANKq, D0q, 0,
         (long)Nq * Nq, (long)Nq * BANKq, (long)Nq * D0q, 0, Bq, 1.f, 0);

    // 4) xg0 = tmp @ gcn0_W + gcn0_b -> feats[:, :, 808:1064]
    gemm(false, tmp, gcn0_W, gcn0_b, nullptr, feats + 808,
         Nq, Gq, D0q, D0q, Gq, BANKq, 0,
         (long)Nq * D0q, 0, (long)Nq * BANKq, 0, Bq, 1.f, 0);

    // 5) GCN + graph-attention layers
    int xoff[NLq]   = {808, 1064};
    int outoff[NLq] = {1064, 1320};
    for (int l = 0; l < NLq; l++) {
        const float* x = feats + xoff[l];
        gemm(false, adj, x, nullptr, nullptr, tmp,
             Nq, Gq, Nq, Nq, BANKq, Gq, 0,
             (long)Nq * Nq, (long)Nq * BANKq, (long)Nq * Gq, 0, Bq, 1.f, 0);
        gemm(false, tmp, gcn_W + (long)l * Gq * Gq, gcn_b + l * Gq, nullptr, x1,
             Nq, Gq, Gq, Gq, Gq, Gq, 0,
             (long)Nq * Gq, 0, (long)Nq * Gq, 0, Bq, 1.f, 1);
        gemm(false, x, attn_Wq + (long)l * Gq * Gq, nullptr, nullptr, xq,
             Nq, Gq, Gq, BANKq, Gq, Gq, 0,
             (long)Nq * BANKq, 0, (long)Nq * Gq, 0, Bq, 1.f, 0);
        gemm(false, x1, attn_Wk + (long)l * Gq * Gq, nullptr, nullptr, xk,
             Nq, Gq, Gq, Gq, Gq, Gq, 0,
             (long)Nq * Gq, 0, (long)Nq * Gq, 0, Bq, 1.f, 0);
        gemm(false, x1, attn_Wv + (long)l * Gq * Gq, nullptr, nullptr, xv,
             Nq, Gq, Gq, Gq, Gq, Gq, 0,
             (long)Nq * Gq, 0, (long)Nq * Gq, 0, Bq, 1.f, 0);
        gemm(true, xq, xk, nullptr, nullptr, att,
             Nq, Nq, Gq, Gq, Gq, Nq, 0,
             (long)Nq * Gq, (long)Nq * Gq, (long)Nq * Nq, 0, Bq, 0.0625f, 0);
        softmax256_kernel<<<Bq * Nq, 256>>>(att);
        gemm(false, att, xv, nullptr, x1, feats + outoff[l],
             Nq, Gq, Nq, Nq, Gq, BANKq, Gq,
             (long)Nq * Nq, (long)Nq * Gq, (long)Nq * BANKq, (long)Nq * Gq, Bq, 1.f, 1);
    }

    // pred weight transpose-split (independent; schedule early)
    {
        dim3 grid((BANK5q + 31) / 32, (BANK5q + 31) / 32);
        transpose_split_kernel<<<grid, dim3(32, 8)>>>(pred_W, wph, wpl, BANK5q, BANK5q);
    }

    // 6) gather paths -> split bf16
    gather_pf_split_kernel<<<MlstmT, 256>>>(feats, path_nodes, ah, al);

    // 7) two LSTM layers (pipelined tensor-core GEMMs)
    for (int layer = 0; layer < 2; layer++) {
        const float* Wih = lstm_Wih + (size_t)layer * BANK4q * BANKq;
        const float* Whh = lstm_Whh + (size_t)layer * BANK4q * BANKq;
        const float* bL  = lstm_b + (size_t)layer * BANK4q;
        split(Wih, w1h, w1l, (size_t)BANK4q * BANKq);
        split(Whh, w2h, w2l, (size_t)BANK4q * BANKq);
        gemm_bf16(ah, al, w1h, w1l, bL, ih, MlstmT, BANK4q, BANKq, 0);
        for (int t = 0; t < Lq; t++) {
            if (t > 0)
                gemm_bf16(sh, sl, w2h, w2l, nullptr, hh, Mlstm, BANK4q, BANKq, 0);
            dim3 grid((BANKq + 255) / 256, Mlstm);
            lstm_cell_kernel<<<grid, 256>>>(ih, hh, sh, sl,
                                            layer == 0 ? ah : nullptr,
                                            layer == 0 ? al : nullptr,
                                            cbuf,
                                            layer == 1 ? hs1 : nullptr, t);
        }
    }

    // 8) masked max-pool over time -> split bf16 (ah/al reused)
    {
        dim3 grid((BANKq + 255) / 256, Mlstm);
        maxpool_split_kernel<<<grid, 256>>>(hs1, path_lens, ah, al);
    }

    // 9) h_f, t_f, query (query emitted as split)
    gather_ht_kernel<<<BPq, 256>>>(feats, h_t_pairs, hf, tf, sh, sl);

    // 10-11) q/k/v projections
    split(mha_inW, w1h, w1l, (size_t)3 * BANKq * BANKq);
    gemm_bf16(sh, sl, w1h, w1l, mha_inb, qb, BPq, BANKq, BANKq, 0);
    gemm_bf16(ah, al, w1h + (size_t)BANKq * BANKq, w1l + (size_t)BANKq * BANKq,
              mha_inb + BANKq, kb, Mlstm, BANKq, BANKq, 0);
    gemm_bf16(ah, al, w1h + 2 * (size_t)BANKq * BANKq, w1l + 2 * (size_t)BANKq * BANKq,
              mha_inb + 2 * BANKq, vb, Mlstm, BANKq, BANKq, 0);

    // 12) tiny attention over K=3 paths (ctx emitted split into sh/sl)
    mha_attn_kernel<<<BPq, 384>>>(qb, kb, vb, path_lens, rel_mask, sh, sl, validany);

    // 13) pinfo = ctx @ mha_outW^T + mha_outb
    split(mha_outW, w2h, w2l, (size_t)BANKq * BANKq);
    gemm_bf16(sh, sl, w2h, w2l, mha_outb, pinfo, BPq, BANKq, BANKq, 0);

    // 14) of (emitted split into ah/al)
    build_of_split_kernel<<<BPq, 256>>>(hf, tf, pinfo, validany, ah, al);

    // 15) hid = relu(of @ pred_W + pred_b)
    gemm_bf16(ah, al, wph, wpl, pred_b, hid, BPq, BANK5q, BANK5q, 1);

    // 16) fused output heads
    head_kernel<<<BPq, 256>>>(hid, mW, mb, bW, bb, out);
}

// round 6
// speedup vs baseline: 2.7461x; 1.4935x over previous
#include <cuda_runtime.h>
#include <cuda_bf16.h>
#include <math.h>
#include <stdio.h>

// ---------------- problem constants ----------------
#define Bq   4
#define Sq   512
#define Nq   256
#define Eq   42
#define Pq   256
#define Kq   3
#define Lq   4
#define HBq  768
#define DTq  20
#define DIq  20
#define Gq   256
#define NLq  2
#define Rq   97
#define NHq  4
#define D0q  808          // HB+DT+DI
#define BANKq 1576        // D0 + G*(NL+1)
#define BANK4q 6304       // 4*BANK
#define BANK5q 7880       // 5*BANK
#define DHq  394          // BANK/NH
#define Mlstm (Bq*Pq*Kq)        // 3072
#define MlstmT (Mlstm*Lq)       // 12288
#define BPq  (Bq*Pq)            // 1024

typedef __nv_bfloat16 bf16;
typedef __nv_bfloat162 bf162;

// ---------------- scratch (static device memory; no allocations allowed) ----------------
__device__ float g_enc   [Bq*Sq*D0q];
__device__ float g_feats [Bq*Nq*BANKq];
__device__ float g_tmp   [Bq*Nq*D0q];
__device__ float g_x1    [Bq*Nq*Gq];
__device__ float g_xq    [Bq*Nq*Gq];
__device__ float g_xk    [Bq*Nq*Gq];
__device__ float g_xv    [Bq*Nq*Gq];
__device__ float g_att   [Bq*Nq*Nq];
__device__ float g_ih    [(size_t)MlstmT*BANK4q];
__device__ float g_hh    [(size_t)Mlstm*BANK4q];
__device__ float g_c     [Mlstm*BANKq];
__device__ float g_hs1   [MlstmT*BANKq];
__device__ float g_hf    [BPq*BANKq];
__device__ float g_tf    [BPq*BANKq];
__device__ float g_q     [BPq*BANKq];
__device__ float g_k     [Mlstm*BANKq];
__device__ float g_v     [Mlstm*BANKq];
__device__ float g_pinfo [BPq*BANKq];
__device__ int   g_validany[BPq];
__device__ float g_hid   [BPq*BANK5q];

// bf16 split scratch
__device__ bf16 g_ah  [(size_t)MlstmT*BANKq];
__device__ bf16 g_al  [(size_t)MlstmT*BANKq];
__device__ bf16 g_sh  [(size_t)Mlstm*BANKq];
__device__ bf16 g_sl  [(size_t)Mlstm*BANKq];
__device__ bf16 g_w1h [(size_t)BANK4q*BANKq];
__device__ bf16 g_w1l [(size_t)BANK4q*BANKq];
__device__ bf16 g_w2h [(size_t)BANK4q*BANKq];
__device__ bf16 g_w2l [(size_t)BANK4q*BANKq];
__device__ bf16 g_wph [(size_t)BANK5q*BANK5q];
__device__ bf16 g_wpl [(size_t)BANK5q*BANK5q];

// ================= fp32 tiled GEMMs (for small GCN ops) =================
#define TS 128
#define KS 8

template <bool TRANSB>
__global__ void __launch_bounds__(256, 2)
gemm_kernel(const float* __restrict__ A, const float* __restrict__ B,
            const float* __restrict__ bias, const float* __restrict__ resid,
            float* __restrict__ C,
            int M, int N, int K,
            int lda, int ldb, int ldc, int ldr,
            long sA, long sB, long sC, long sR,
            float alpha, int act)
{
    int bz = blockIdx.z;
    A += bz * sA; B += bz * sB; C += bz * sC;
    if (resid) resid += bz * sR;

    int row0 = blockIdx.y * TS;
    int col0 = blockIdx.x * TS;

    __shared__ float As[KS][TS];
    __shared__ float Bs[KS][TS + 4];

    int tid = threadIdx.x;
    int tx = tid & 15, ty = tid >> 4;

    float acc[8][8];
#pragma unroll
    for (int i = 0; i < 8; i++)
#pragma unroll
        for (int j = 0; j < 8; j++) acc[i][j] = 0.f;

    for (int k0 = 0; k0 < K; k0 += KS) {
#pragma unroll
        for (int l = 0; l < 4; l++) {
            int idx = tid + l * 256;
            int m = idx >> 3, kk = idx & 7;
            int gr = row0 + m, gk = k0 + kk;
            As[kk][m] = (gr < M && gk < K) ? A[(long)gr * lda + gk] : 0.f;
        }
#pragma unroll
        for (int l = 0; l < 4; l++) {
            int idx = tid + l * 256;
            if (TRANSB) {
                int n = idx >> 3, kk = idx & 7;
                int gn = col0 + n, gk = k0 + kk;
                Bs[kk][n] = (gn < N && gk < K) ? B[(long)gn * ldb + gk] : 0.f;
            } else {
                int kk = idx >> 7, n = idx & 127;
                int gn = col0 + n, gk = k0 + kk;
                Bs[kk][n] = (gn < N && gk < K) ? B[(long)gk * ldb + gn] : 0.f;
            }
        }
        __syncthreads();
#pragma unroll
        for (int kk = 0; kk < KS; kk++) {
            float a[8], b[8];
#pragma unroll
            for (int i = 0; i < 8; i++) a[i] = As[kk][ty + 16 * i];
#pragma unroll
            for (int j = 0; j < 8; j++) b[j] = Bs[kk][tx + 16 * j];
#pragma unroll
            for (int i = 0; i < 8; i++)
#pragma unroll
                for (int j = 0; j < 8; j++)
                    acc[i][j] = fmaf(a[i], b[j], acc[i][j]);
        }
        __syncthreads();
    }

#pragma unroll
    for (int i = 0; i < 8; i++) {
        int r = row0 + ty + 16 * i;
        if (r >= M) continue;
#pragma unroll
        for (int j = 0; j < 8; j++) {
            int cc = col0 + tx + 16 * j;
            if (cc >= N) continue;
            float v = acc[i][j] * alpha;
            if (bias) v += bias[cc];
            if (act == 1) v = fmaxf(v, 0.f);
            if (resid) v += resid[(long)r * ldr + cc];
            C[(long)r * ldc + cc] = v;
        }
    }
}

template <bool TRANSB>
__global__ void __launch_bounds__(256)
gemm64_kernel(const float* __restrict__ A, const float* __restrict__ B,
              const float* __restrict__ bias, const float* __restrict__ resid,
              float* __restrict__ C,
              int M, int N, int K,
              int lda, int ldb, int ldc, int ldr,
              long sA, long sB, long sC, long sR,
              float alpha, int act)
{
    int bz = blockIdx.z;
    A += bz * sA; B += bz * sB; C += bz * sC;
    if (resid) resid += bz * sR;

    int row0 = blockIdx.y * 64;
    int col0 = blockIdx.x * 64;

    __shared__ float As[16][64 + 1];
    __shared__ float Bs[16][64 + 1];

    int tid = threadIdx.x;
    int tx = tid & 15, ty = tid >> 4;

    float acc[4][4];
#pragma unroll
    for (int i = 0; i < 4; i++)
#pragma unroll
        for (int j = 0; j < 4; j++) acc[i][j] = 0.f;

    for (int k0 = 0; k0 < K; k0 += 16) {
#pragma unroll
        for (int l = 0; l < 4; l++) {
            int idx = tid + l * 256;
            int m = idx >> 4, kk = idx & 15;
            int gr = row0 + m, gk = k0 + kk;
            As[kk][m] = (gr < M && gk < K) ? A[(long)gr * lda + gk] : 0.f;
        }
#pragma unroll
        for (int l = 0; l < 4; l++) {
            int idx = tid + l * 256;
            if (TRANSB) {
                int n = idx >> 4, kk = idx & 15;
                int gn = col0 + n, gk = k0 + kk;
                Bs[kk][n] = (gn < N && gk < K) ? B[(long)gn * ldb + gk] : 0.f;
            } else {
                int kk = idx >> 6, n = idx & 63;
                int gn = col0 + n, gk = k0 + kk;
                Bs[kk][n] = (gn < N && gk < K) ? B[(long)gk * ldb + gn] : 0.f;
            }
        }
        __syncthreads();
#pragma unroll
        for (int kk = 0; kk < 16; kk++) {
            float a[4], b[4];
#pragma unroll
            for (int i = 0; i < 4; i++) a[i] = As[kk][ty + 16 * i];
#pragma unroll
            for (int j = 0; j < 4; j++) b[j] = Bs[kk][tx + 16 * j];
#pragma unroll
            for (int i = 0; i < 4; i++)
#pragma unroll
                for (int j = 0; j < 4; j++)
                    acc[i][j] = fmaf(a[i], b[j], acc[i][j]);
        }
        __syncthreads();
    }

#pragma unroll
    for (int i = 0; i < 4; i++) {
        int r = row0 + ty + 16 * i;
        if (r >= M) continue;
#pragma unroll
        for (int j = 0; j < 4; j++) {
            int cc = col0 + tx + 16 * j;
            if (cc >= N) continue;
            float v = acc[i][j] * alpha;
            if (bias) v += bias[cc];
            if (act == 1) v = fmaxf(v, 0.f);
            if (resid) v += resid[(long)r * ldr + cc];
            C[(long)r * ldc + cc] = v;
        }
    }
}

static void gemm(bool transB,
                 const float* A, const float* B, const float* bias, const float* resid, float* C,
                 int M, int N, int K, int lda, int ldb, int ldc, int ldr,
                 long sA, long sB, long sC, long sR, int batch, float alpha, int act)
{
    if (M <= 256) {
        dim3 grid((N + 63) / 64, (M + 63) / 64, batch);
        if (transB)
            gemm64_kernel<true><<<grid, 256>>>(A, B, bias, resid, C, M, N, K, lda, ldb, ldc, ldr, sA, sB, sC, sR, alpha, act);
        else
            gemm64_kernel<false><<<grid, 256>>>(A, B, bias, resid, C, M, N, K, lda, ldb, ldc, ldr, sA, sB, sC, sR, alpha, act);
    } else {
        dim3 grid((N + TS - 1) / TS, (M + TS - 1) / TS, batch);
        if (transB)
            gemm_kernel<true><<<grid, 256>>>(A, B, bias, resid, C, M, N, K, lda, ldb, ldc, ldr, sA, sB, sC, sR, alpha, act);
        else
            gemm_kernel<false><<<grid, 256>>>(A, B, bias, resid, C, M, N, K, lda, ldb, ldc, ldr, sA, sB, sC, sR, alpha, act);
    }
}

// ================= bf16 split-precision tensor-core GEMM (pipelined, RAW-free) =================
// C(MxN) = A(MxK) @ B(NxK)^T + bias, A = Ah+Al, B = Bh+Bl.
// acc += Ah*Bh + Ah*Bl + Al*Bh  — issued as 3 passes of 16 independent MMAs so the
// same accumulator is only re-touched every 16 HMMAs (covers HMMA latency).
#define LDSB 40                    // padded row stride in bf16 (80B -> conflict-free ldmatrix)
#define GSTG 3                     // pipeline stages
#define PLANE_E (128*LDSB)         // elems per plane
#define PLANE_B (PLANE_E*2)        // bytes per plane (10240)
#define STAGE_B (4*PLANE_B)        // bytes per stage  (40960)

#define MMA_BF16(d, a, b) asm volatile( \
    "mma.sync.aligned.m16n8k16.row.col.f32.bf16.bf16.f32 " \
    "{%0,%1,%2,%3}, {%4,%5,%6,%7}, {%8,%9}, {%0,%1,%2,%3};" \
    : "+f"((d)[0]), "+f"((d)[1]), "+f"((d)[2]), "+f"((d)[3]) \
    : "r"((a)[0]), "r"((a)[1]), "r"((a)[2]), "r"((a)[3]), "r"((b)[0]), "r"((b)[1]))

#define LDSM4(r, addr) asm volatile( \
    "ldmatrix.sync.aligned.m8n8.x4.shared.b16 {%0,%1,%2,%3}, [%4];" \
    : "=r"((r)[0]), "=r"((r)[1]), "=r"((r)[2]), "=r"((r)[3]) : "r"(addr))

__device__ __forceinline__ void cpasync16(unsigned saddr, const void* g, int srcbytes)
{
    asm volatile("cp.async.cg.shared.global [%0], [%1], 16, %2;\n"
                 :: "r"(saddr), "l"(g), "r"(srcbytes));
}

__device__ __forceinline__ void gbf_prefetch(
    const bf16* __restrict__ Ah, const bf16* __restrict__ Al,
    const bf16* __restrict__ Bh, const bf16* __restrict__ Bl,
    long row0, long col0, int M, int N, int K,
    int kt, int T, unsigned sbase, int stg, int tid)
{
    if (kt >= T) return;
    long k0 = (long)kt * 32;
    unsigned sst = sbase + (unsigned)stg * STAGE_B;
#pragma unroll
    for (int i = 0; i < 2; i++) {
        int c = tid + i * 256;          // 512 chunks of 16B per plane
        int r = c >> 2;
        int ko = (c & 3) * 8;
        long gk = k0 + ko;
        bool kok = gk < K;
        long gkc = kok ? gk : 0;
        unsigned soff = (unsigned)((r * LDSB + ko) * 2);
        {
            long gr = row0 + r;
            bool ok = kok && (gr < M);
            long grc = ok ? gr : 0;
            int nb = ok ? 16 : 0;
            cpasync16(sst + soff,            Ah + grc * K + gkc, nb);
            cpasync16(sst + PLANE_B + soff,  Al + grc * K + gkc, nb);
        }
        {
            long gn = col0 + r;
            bool ok = kok && (gn < N);
            long gnc = ok ? gn : 0;
            int nb = ok ? 16 : 0;
            cpasync16(sst + 2 * PLANE_B + soff, Bh + gnc * K + gkc, nb);
            cpasync16(sst + 3 * PLANE_B + soff, Bl + gnc * K + gkc, nb);
        }
    }
}

__global__ void __launch_bounds__(256)
gemm_bf16_kernel(const bf16* __restrict__ Ah, const bf16* __restrict__ Al,
                 const bf16* __restrict__ Bh, const bf16* __restrict__ Bl,
                 const float* __restrict__ bias, float* __restrict__ C,
                 int M, int N, int K, int act)
{
    extern __shared__ __align__(16) bf16 dsm[];
    unsigned sbase = (unsigned)__cvta_generic_to_shared(dsm);

    int tid = threadIdx.x;
    int warp = tid >> 5, lane = tid & 31;
    int wm = (warp & 1) * 64;
    int wn = (warp >> 1) * 32;
    long row0 = (long)blockIdx.y * 128;
    long col0 = (long)blockIdx.x * 128;

    float acc[4][4][4];
#pragma unroll
    for (int a = 0; a < 4; a++)
#pragma unroll
        for (int b = 0; b < 4; b++)
#pragma unroll
            for (int c = 0; c < 4; c++) acc[a][b][c] = 0.f;

    int am_r = (lane & 7) + ((lane >> 3) & 1) * 8;
    int a_c8 = ((lane >> 4) & 1) * 8;
    int b_r  = (lane & 7) + ((lane >> 4) & 1) * 8;
    int b_c8 = ((lane >> 3) & 1) * 8;

    int T = (K + 31) / 32;

    // prologue: fill the pipeline
#pragma unroll
    for (int kt = 0; kt < GSTG; kt++) {
        gbf_prefetch(Ah, Al, Bh, Bl, row0, col0, M, N, K, kt, T, sbase, kt, tid);
        asm volatile("cp.async.commit_group;\n");
    }

    for (int kt = 0; kt < T; kt++) {
        asm volatile("cp.async.wait_group %0;\n" :: "n"(GSTG - 1));
        __syncthreads();

        int stg = kt % GSTG;
        unsigned sst = sbase + (unsigned)stg * STAGE_B;
        unsigned aB = sst;
        unsigned bB = sst + 2 * PLANE_B;

#pragma unroll
        for (int ks = 0; ks < 2; ks++) {
            int kb = ks * 16;
            unsigned bh[2][4], bl[2][4];
#pragma unroll
            for (int pp = 0; pp < 2; pp++) {
                unsigned addr = bB + (unsigned)(((wn + pp * 16 + b_r) * LDSB + kb + b_c8) * 2);
                LDSM4(bh[pp], addr);
                LDSM4(bl[pp], addr + PLANE_B);
            }
            unsigned ahf[4][4], alf[4][4];
#pragma unroll
            for (int mi = 0; mi < 4; mi++) {
                unsigned addr = aB + (unsigned)(((wm + mi * 16 + am_r) * LDSB + kb + a_c8) * 2);
                LDSM4(ahf[mi], addr);
                LDSM4(alf[mi], addr + PLANE_B);
            }
            // pass 1: ah*bh — 16 independent MMAs
#pragma unroll
            for (int mi = 0; mi < 4; mi++)
#pragma unroll
                for (int ni = 0; ni < 4; ni++)
                    MMA_BF16(acc[mi][ni], ahf[mi], (&bh[ni >> 1][(ni & 1) * 2]));
            // pass 2: ah*bl
#pragma unroll
            for (int mi = 0; mi < 4; mi++)
#pragma unroll
                for (int ni = 0; ni < 4; ni++)
                    MMA_BF16(acc[mi][ni], ahf[mi], (&bl[ni >> 1][(ni & 1) * 2]));
            // pass 3: al*bh
#pragma unroll
            for (int mi = 0; mi < 4; mi++)
#pragma unroll
                for (int ni = 0; ni < 4; ni++)
                    MMA_BF16(acc[mi][ni], alf[mi], (&bh[ni >> 1][(ni & 1) * 2]));
        }
        __syncthreads();
        gbf_prefetch(Ah, Al, Bh, Bl, row0, col0, M, N, K, kt + GSTG, T, sbase, stg, tid);
        asm volatile("cp.async.commit_group;\n");
    }

    // ---- epilogue ----
#pragma unroll
    for (int mi = 0; mi < 4; mi++) {
#pragma unroll
        for (int ni = 0; ni < 4; ni++) {
            long r = row0 + wm + mi * 16 + (lane >> 2);
            long c = col0 + wn + ni * 8 + (lane & 3) * 2;
#pragma unroll
            for (int half = 0; half < 2; half++) {
                long rr = r + half * 8;
                if (rr >= M) continue;
#pragma unroll
                for (int e = 0; e < 2; e++) {
                    long cc = c + e;
                    if (cc >= N) continue;
                    float v = acc[mi][ni][half * 2 + e];
                    if (bias) v += bias[cc];
                    if (act == 1) v = fmaxf(v, 0.f);
                    C[(size_t)rr * N + cc] = v;
                }
            }
        }
    }
}

static void gemm_bf16(const bf16* Ah, const bf16* Al, const bf16* Bh, const bf16* Bl,
                      const float* bias, float* C, int M, int N, int K, int act)
{
    static int attr_done = 0;
    if (!attr_done) {
        cudaFuncSetAttribute(gemm_bf16_kernel,
                             cudaFuncAttributeMaxDynamicSharedMemorySize, GSTG * STAGE_B);
        attr_done = 1;
    }
    dim3 grid((N + 127) / 128, (M + 127) / 128);
    gemm_bf16_kernel<<<grid, 256, GSTG * STAGE_B>>>(Ah, Al, Bh, Bl, bias, C, M, N, K, act);
}

// ================= conversion kernels =================
__device__ __forceinline__ void split1(float f, bf16& h, bf16& l)
{
    h = __float2bfloat16(f);
    l = __float2bfloat16(f - __bfloat162float(h));
}

__global__ void split_kernel(const float* __restrict__ x, bf16* __restrict__ hi,
                             bf16* __restrict__ lo, size_t n4)
{
    size_t i = (size_t)blockIdx.x * blockDim.x + threadIdx.x;
    if (i >= n4) return;
    float4 f = ((const float4*)x)[i];
    bf16 h0, l0, h1, l1, h2, l2, h3, l3;
    split1(f.x, h0, l0); split1(f.y, h1, l1); split1(f.z, h2, l2); split1(f.w, h3, l3);
    bf162 vh0; vh0.x = h0; vh0.y = h1;
    bf162 vh1; vh1.x = h2; vh1.y = h3;
    bf162 vl0; vl0.x = l0; vl0.y = l1;
    bf162 vl1; vl1.x = l2; vl1.y = l3;
    ((bf162*)hi)[i * 2] = vh0; ((bf162*)hi)[i * 2 + 1] = vh1;
    ((bf162*)lo)[i * 2] = vl0; ((bf162*)lo)[i * 2 + 1] = vl1;
}

static void split(const float* x, bf16* hi, bf16* lo, size_t n)
{
    size_t n4 = n / 4;
    split_kernel<<<(unsigned)((n4 + 255) / 256), 256>>>(x, hi, lo, n4);
}

__global__ void transpose_split_kernel(const float* __restrict__ B, bf16* __restrict__ Th,
                                       bf16* __restrict__ Tl, int K, int N)
{
    __shared__ float tile[32][33];
    int k0 = blockIdx.y * 32, n0 = blockIdx.x * 32;
    int tx = threadIdx.x, ty = threadIdx.y;  // 32 x 8
#pragma unroll
    for (int i = 0; i < 32; i += 8) {
        int k = k0 + ty + i, n = n0 + tx;
        tile[ty + i][tx] = (k < K && n < N) ? B[(size_t)k * N + n] : 0.f;
    }
    __syncthreads();
#pragma unroll
    for (int i = 0; i < 32; i += 8) {
        int n = n0 + ty + i, k = k0 + tx;
        if (n < N && k < K) {
            float f = tile[tx][ty + i];
            bf16 h, l; split1(f, h, l);
            Th[(size_t)n * K + k] = h;
            Tl[(size_t)n * K + k] = l;
        }
    }
}

// ---------------- small custom kernels ----------------
__global__ void build_enc_kernel(const float* __restrict__ eo, const int* __restrict__ etype,
                                 const int* __restrict__ eid, const float* __restrict__ temb,
                                 const float* __restrict__ iemb, float* __restrict__ enc)
{
    int bs = blockIdx.x;
    const float* src = eo + (long)bs * HBq;
    float* dst = enc + (long)bs * D0q;
    int ty = etype[bs], idv = eid[bs];
    for (int j = threadIdx.x; j < D0q; j += blockDim.x) {
        float v;
        if (j < HBq)            v = src[j];
        else if (j < HBq + DTq) v = temb[ty * DTq + (j - HBq)];
        else                    v = iemb[idv * DIq + (j - HBq - DTq)];
        dst[j] = v;
    }
}

__global__ void softmax256_kernel(float* __restrict__ x)
{
    int row = blockIdx.x;
    int tid = threadIdx.x;
    float v = x[(long)row * 256 + tid];
    __shared__ float red[8];
    int lane = tid & 31, warp = tid >> 5;
    float m = v;
#pragma unroll
    for (int o = 16; o > 0; o >>= 1) m = fmaxf(m, __shfl_xor_sync(0xffffffffu, m, o));
    if (lane == 0) red[warp] = m;
    __syncthreads();
    if (tid == 0) {
        float mm = red[0];
        for (int w = 1; w < 8; w++) mm = fmaxf(mm, red[w]);
        red[0] = mm;
    }
    __syncthreads();
    float mx = red[0];
    float e = expf(v - mx);
    float s = e;
#pragma unroll
    for (int o = 16; o > 0; o >>= 1) s += __shfl_xor_sync(0xffffffffu, s, o);
    __shared__ float red2[8];
    if (lane == 0) red2[warp] = s;
    __syncthreads();
    if (tid == 0) {
        float ss = 0.f;
        for (int w = 0; w < 8; w++) ss += red2[w];
        red2[0] = ss;
    }
    __syncthreads();
    x[(long)row * 256 + tid] = e / red2[0];
}

__global__ void gather_pf_split_kernel(const float* __restrict__ feats, const int* __restrict__ nodes,
                                       bf16* __restrict__ hi, bf16* __restrict__ lo)
{
    int row = blockIdx.x;                 // 0..12287
    int b = row / (Pq * Kq * Lq);
    int node = nodes[row];
    const float* src = feats + ((size_t)b * Nq + node) * BANKq;
    size_t base = (size_t)row * BANKq;
    for (int j = threadIdx.x; j < BANKq; j += blockDim.x) {
        bf16 h, l; split1(src[j], h, l);
        hi[base + j] = h;
        lo[base + j] = l;
    }
}

__device__ __forceinline__ float sigmoidf_(float x) { return 1.f / (1.f + expf(-x)); }

__global__ void lstm_cell_kernel(const float* __restrict__ ih, const float* __restrict__ hh,
                                 bf16* __restrict__ h_hi, bf16* __restrict__ h_lo,
                                 bf16* __restrict__ seq_hi, bf16* __restrict__ seq_lo,
                                 float* __restrict__ c, float* __restrict__ hs, int t)
{
    int i = blockIdx.y;
    int j = blockIdx.x * blockDim.x + threadIdx.x;
    if (j >= BANKq) return;
    const float* g = ih + ((size_t)i * Lq + t) * BANK4q;
    float gi = g[j], gf = g[BANKq + j], gg = g[2 * BANKq + j], go = g[3 * BANKq + j];
    float cp = 0.f;
    if (t > 0) {
        const float* hr = hh + (size_t)i * BANK4q;
        gi += hr[j]; gf += hr[BANKq + j]; gg += hr[2 * BANKq + j]; go += hr[3 * BANKq + j];
        cp = c[(size_t)i * BANKq + j];
    }
    float cn = sigmoidf_(gf) * cp + sigmoidf_(gi) * tanhf(gg);
    float hn = sigmoidf_(go) * tanhf(cn);
    c[(size_t)i * BANKq + j] = cn;
    bf16 h, l; split1(hn, h, l);
    h_hi[(size_t)i * BANKq + j] = h;
    h_lo[(size_t)i * BANKq + j] = l;
    if (seq_hi) {
        seq_hi[((size_t)i * Lq + t) * BANKq + j] = h;
        seq_lo[((size_t)i * Lq + t) * BANKq + j] = l;
    }
    if (hs) hs[((size_t)i * Lq + t) * BANKq + j] = hn;
}

__global__ void maxpool_split_kernel(const float* __restrict__ hs, const int* __restrict__ lens,
                                     bf16* __restrict__ hi, bf16* __restrict__ lo)
{
    int i = blockIdx.y;
    int j = blockIdx.x * blockDim.x + threadIdx.x;
    if (j >= BANKq) return;
    int len = lens[i];
    float m = -1e9f;
    const float* base = hs + (size_t)i * Lq * BANKq + j;
    for (int t = 0; t < Lq; t++)
        if (t < len) m = fmaxf(m, base[(size_t)t * BANKq]);
    float r = (len > 0) ? m : 0.f;
    bf16 h, l; split1(r, h, l);
    hi[(size_t)i * BANKq + j] = h;
    lo[(size_t)i * BANKq + j] = l;
}

__global__ void gather_ht_kernel(const float* __restrict__ feats, const int* __restrict__ htp,
                                 float* __restrict__ hf, float* __restrict__ tf,
                                 bf16* __restrict__ qh, bf16* __restrict__ ql)
{
    int bp = blockIdx.x;
    int b = bp / Pq;
    int h0 = htp[bp * 2 + 0], t0 = htp[bp * 2 + 1];
    h0 = (h0 == 0) ? 0 : h0 - 1;
    t0 = (t0 == 0) ? 0 : t0 - 1;
    const float* hsrc = feats + ((size_t)b * Nq + (Nq - Eq) + h0) * BANKq;
    const float* tsrc = feats + ((size_t)b * Nq + (Nq - Eq) + t0) * BANKq;
    for (int j = threadIdx.x; j < BANKq; j += blockDim.x) {
        float hv = hsrc[j], tv = tsrc[j];
        hf[(size_t)bp * BANKq + j] = hv;
        tf[(size_t)bp * BANKq + j] = tv;
        bf16 h, l; split1(hv - tv, h, l);
        qh[(size_t)bp * BANKq + j] = h;
        ql[(size_t)bp * BANKq + j] = l;
    }
}

__global__ void mha_attn_kernel(const float* __restrict__ q, const float* __restrict__ k,
                                const float* __restrict__ v, const int* __restrict__ plens,
                                const float* __restrict__ rmask,
                                bf16* __restrict__ ctx_hi, bf16* __restrict__ ctx_lo,
                                int* __restrict__ validany)
{
    int bp = blockIdx.x;
    int tid = threadIdx.x;
    int warp = tid >> 5, lane = tid & 31;
    __shared__ float sc[NHq][Kq];
    __shared__ float aw[NHq][Kq];
    __shared__ int vm[Kq];
    if (tid < Kq) vm[tid] = (rmask[bp] > 0.f && plens[bp * Kq + tid] > 0) ? 1 : 0;
    __syncthreads();
    {
        int h = warp / Kq, kk = warp % Kq;
        const float* qh = q + (size_t)bp * BANKq + h * DHq;
        const float* kh = k + ((size_t)bp * Kq + kk) * BANKq + h * DHq;
        float s = 0.f;
        for (int d = lane; d < DHq; d += 32) s += qh[d] * kh[d];
#pragma unroll
        for (int o = 16; o > 0; o >>= 1) s += __shfl_xor_sync(0xffffffffu, s, o);
        if (lane == 0) {
            s = s / sqrtf((float)DHq);
            sc[h][kk] = vm[kk] ? s : -1e9f;
        }
    }
    __syncthreads();
    if (tid < NHq) {
        int h = tid;
        float m = fmaxf(fmaxf(sc[h][0], sc[h][1]), sc[h][2]);
        float e0 = expf(sc[h][0] - m), e1 = expf(sc[h][1] - m), e2 = expf(sc[h][2] - m);
        float s = e0 + e1 + e2;
        aw[h][0] = e0 / s; aw[h][1] = e1 / s; aw[h][2] = e2 / s;
    }
    if (tid == 0) validany[bp] = (vm[0] | vm[1] | vm[2]);
    __syncthreads();
    for (int j = tid; j < BANKq; j += blockDim.x) {
        int h = j / DHq;
        const float* vb = v + (size_t)bp * Kq * BANKq + j;
        float r = aw[h][0] * vb[0] + aw[h][1] * vb[BANKq] + aw[h][2] * vb[2 * BANKq];
        bf16 hh2, ll2; split1(r, hh2, ll2);
        ctx_hi[(size_t)bp * BANKq + j] = hh2;
        ctx_lo[(size_t)bp * BANKq + j] = ll2;
    }
}

__global__ void build_of_split_kernel(const float* __restrict__ hf, const float* __restrict__ tf,
                                      const float* __restrict__ pinfo, const int* __restrict__ validany,
                                      bf16* __restrict__ oh, bf16* __restrict__ ol)
{
    int bp = blockIdx.x;
    int va = validany[bp];
    const float* hr = hf + (size_t)bp * BANKq;
    const float* tr = tf + (size_t)bp * BANKq;
    const float* pr = pinfo + (size_t)bp * BANKq;
    size_t base = (size_t)bp * BANK5q;
    for (int j = threadIdx.x; j < BANK5q; j += blockDim.x) {
        int seg = j / BANKq, jj = j - seg * BANKq;
        float v;
        if (seg == 0)      v = hr[jj];
        else if (seg == 1) v = tr[jj];
        else if (seg == 2) v = fabsf(hr[jj] - tr[jj]);
        else if (seg == 3) v = hr[jj] * tr[jj];
        else               v = va ? pr[jj] : 0.f;
        bf16 h, l; split1(v, h, l);
        oh[base + j] = h;
        ol[base + j] = l;
    }
}

__global__ void __launch_bounds__(256)
head_kernel(const float* __restrict__ hid, const float* __restrict__ mW,
            const float* __restrict__ mb, const float* __restrict__ bW,
            const float* __restrict__ bb, float* __restrict__ out)
{
    int m = blockIdx.x;
    __shared__ float srow[BANK5q];
    __shared__ float part[2][Rq + 2];
    const float* hr = hid + (size_t)m * BANK5q;
    for (int j = threadIdx.x; j < BANK5q; j += 256) srow[j] = hr[j];
    __syncthreads();
    int t = threadIdx.x;
    const int NT = Rq + 2;  // 99
    if (t < 2 * NT) {
        int ks = t / NT, n = t - ks * NT;
        int k0 = ks * (BANK5q / 2), k1 = k0 + BANK5q / 2;
        float acc = 0.f;
        if (n < Rq) {
#pragma unroll 8
            for (int k = k0; k < k1; k++) acc += srow[k] * mW[(size_t)k * Rq + n];
        } else {
            int nb = n - Rq;
#pragma unroll 8
            for (int k = k0; k < k1; k++) acc += srow[k] * bW[(size_t)k * 2 + nb];
        }
        part[ks][n] = acc;
    }
    __syncthreads();
    if (t < NT) {
        float v = part[0][t] + part[1][t];
        if (t < Rq) out[(size_t)m * Rq + t] = v + mb[t];
        else        out[(size_t)BPq * Rq + (size_t)m * 2 + (t - Rq)] = v + bb[t - Rq];
    }
}

// ---------------- orchestration ----------------
extern "C" void kernel_launch(void* const* d_in, const int* in_sizes, int n_in,
                              void* d_out, int out_size)
{
    const float* encoder_outputs = (const float*)d_in[0];
    const int*   entity_type     = (const int*)  d_in[1];
    const int*   entity_id       = (const int*)  d_in[2];
    const float* sub2words       = (const float*)d_in[3];
    const float* adj             = (const float*)d_in[4];
    const int*   h_t_pairs       = (const int*)  d_in[5];
    const float* rel_mask        = (const float*)d_in[6];
    const int*   path_nodes      = (const int*)  d_in[7];
    const int*   path_lens       = (const int*)  d_in[8];
    const float* type_emb        = (const float*)d_in[9];
    const float* id_emb          = (const float*)d_in[10];
    const float* gcn0_W          = (const float*)d_in[11];
    const float* gcn0_b          = (const float*)d_in[12];
    const float* gcn_W           = (const float*)d_in[13];
    const float* gcn_b           = (const float*)d_in[14];
    const float* attn_Wq         = (const float*)d_in[15];
    const float* attn_Wk         = (const float*)d_in[16];
    const float* attn_Wv         = (const float*)d_in[17];
    const float* lstm_Wih        = (const float*)d_in[18];
    const float* lstm_Whh        = (const float*)d_in[19];
    const float* lstm_b          = (const float*)d_in[20];
    const float* mha_inW         = (const float*)d_in[21];
    const float* mha_inb         = (const float*)d_in[22];
    const float* mha_outW        = (const float*)d_in[23];
    const float* mha_outb        = (const float*)d_in[24];
    const float* pred_W          = (const float*)d_in[25];
    const float* pred_b          = (const float*)d_in[26];
    const float* mW              = (const float*)d_in[27];
    const float* mb              = (const float*)d_in[28];
    const float* bW              = (const float*)d_in[29];
    const float* bb              = (const float*)d_in[30];
    float* out = (float*)d_out;

    void* p;
#define SYMF(var, sym) cudaGetSymbolAddress(&p, sym); float* var = (float*)p;
#define SYMB(var, sym) cudaGetSymbolAddress(&p, sym); bf16* var = (bf16*)p;
    SYMF(enc,   g_enc);    SYMF(feats, g_feats);  SYMF(tmp,   g_tmp);
    SYMF(x1,    g_x1);     SYMF(xq,    g_xq);     SYMF(xk,    g_xk);
    SYMF(xv,    g_xv);     SYMF(att,   g_att);
    SYMF(ih,    g_ih);     SYMF(hh,    g_hh);
    SYMF(cbuf,  g_c);      SYMF(hs1,   g_hs1);
    SYMF(hf,    g_hf);     SYMF(tf,    g_tf);
    SYMF(qb,    g_q);      SYMF(kb,    g_k);      SYMF(vb,    g_v);
    SYMF(pinfo, g_pinfo);  SYMF(hid,   g_hid);
    SYMB(ah,  g_ah);  SYMB(al,  g_al);
    SYMB(sh,  g_sh);  SYMB(sl,  g_sl);
    SYMB(w1h, g_w1h); SYMB(w1l, g_w1l);
    SYMB(w2h, g_w2h); SYMB(w2l, g_w2l);
    SYMB(wph, g_wph); SYMB(wpl, g_wpl);
    cudaGetSymbolAddress(&p, g_validany); int* validany = (int*)p;
#undef SYMF
#undef SYMB

    // 1) enc = concat(encoder_outputs, type_emb[...], id_emb[...])
    build_enc_kernel<<<Bq * Sq, 256>>>(encoder_outputs, entity_type, entity_id, type_emb, id_emb, enc);

    // 2) x0 = sub2words @ enc -> feats[:, :, 0:808]
    gemm(false, sub2words, enc, nullptr, nullptr, feats,
         Nq, D0q, Sq, Sq, D0q, BANKq, 0,
         (long)Nq * Sq, (long)Sq * D0q, (long)Nq * BANKq, 0, Bq, 1.f, 0);

    // 3) tmp = adj @ x0
    gemm(false, adj, feats, nullptr, nullptr, tmp,
         Nq, D0q, Nq, Nq, BANKq, D0q, 0,
         (long)Nq * Nq, (long)Nq * BANKq, (long)Nq * D0q, 0, Bq, 1.f, 0);

    // 4) xg0 = tmp @ gcn0_W + gcn0_b -> feats[:, :, 808:1064]
    gemm(false, tmp, gcn0_W, gcn0_b, nullptr, feats + 808,
         Nq, Gq, D0q, D0q, Gq, BANKq, 0,
         (long)Nq * D0q, 0, (long)Nq * BANKq, 0, Bq, 1.f, 0);

    // 5) GCN + graph-attention layers
    int xoff[NLq]   = {808, 1064};
    int outoff[NLq] = {1064, 1320};
    for (int l = 0; l < NLq; l++) {
        const float* x = feats + xoff[l];
        gemm(false, adj, x, nullptr, nullptr, tmp,
             Nq, Gq, Nq, Nq, BANKq, Gq, 0,
             (long)Nq * Nq, (long)Nq * BANKq, (long)Nq * Gq, 0, Bq, 1.f, 0);
        gemm(false, tmp, gcn_W + (long)l * Gq * Gq, gcn_b + l * Gq, nullptr, x1,
             Nq, Gq, Gq, Gq, Gq, Gq, 0,
             (long)Nq * Gq, 0, (long)Nq * Gq, 0, Bq, 1.f, 1);
        gemm(false, x, attn_Wq + (long)l * Gq * Gq, nullptr, nullptr, xq,
             Nq, Gq, Gq, BANKq, Gq, Gq, 0,
             (long)Nq * BANKq, 0, (long)Nq * Gq, 0, Bq, 1.f, 0);
        gemm(false, x1, attn_Wk + (long)l * Gq * Gq, nullptr, nullptr, xk,
             Nq, Gq, Gq, Gq, Gq, Gq, 0,
             (long)Nq * Gq, 0, (long)Nq * Gq, 0, Bq, 1.f, 0);
        gemm(false, x1, attn_Wv + (long)l * Gq * Gq, nullptr, nullptr, xv,
             Nq, Gq, Gq, Gq, Gq, Gq, 0,
             (long)Nq * Gq, 0, (long)Nq * Gq, 0, Bq, 1.f, 0);
        gemm(true, xq, xk, nullptr, nullptr, att,
             Nq, Nq, Gq, Gq, Gq, Nq, 0,
             (long)Nq * Gq, (long)Nq * Gq, (long)Nq * Nq, 0, Bq, 0.0625f, 0);
        softmax256_kernel<<<Bq * Nq, 256>>>(att);
        gemm(false, att, xv, nullptr, x1, feats + outoff[l],
             Nq, Gq, Nq, Nq, Gq, BANKq, Gq,
             (long)Nq * Nq, (long)Nq * Gq, (long)Nq * BANKq, (long)Nq * Gq, Bq, 1.f, 1);
    }

    // pred weight transpose-split (independent)
    {
        dim3 grid((BANK5q + 31) / 32, (BANK5q + 31) / 32);
        transpose_split_kernel<<<grid, dim3(32, 8)>>>(pred_W, wph, wpl, BANK5q, BANK5q);
    }

    // 6) gather paths -> split bf16
    gather_pf_split_kernel<<<MlstmT, 256>>>(feats, path_nodes, ah, al);

    // 7) two LSTM layers
    for (int layer = 0; layer < 2; layer++) {
        const float* Wih = lstm_Wih + (size_t)layer * BANK4q * BANKq;
        const float* Whh = lstm_Whh + (size_t)layer * BANK4q * BANKq;
        const float* bL  = lstm_b + (size_t)layer * BANK4q;
        split(Wih, w1h, w1l, (size_t)BANK4q * BANKq);
        split(Whh, w2h, w2l, (size_t)BANK4q * BANKq);
        gemm_bf16(ah, al, w1h, w1l, bL, ih, MlstmT, BANK4q, BANKq, 0);
        for (int t = 0; t < Lq; t++) {
            if (t > 0)
                gemm_bf16(sh, sl, w2h, w2l, nullptr, hh, Mlstm, BANK4q, BANKq, 0);
            dim3 grid((BANKq + 255) / 256, Mlstm);
            lstm_cell_kernel<<<grid, 256>>>(ih, hh, sh, sl,
                                            layer == 0 ? ah : nullptr,
                                            layer == 0 ? al : nullptr,
                                            cbuf,
                                            layer == 1 ? hs1 : nullptr, t);
        }
    }

    // 8) masked max-pool over time -> split bf16 (ah/al reused)
    {
        dim3 grid((BANKq + 255) / 256, Mlstm);
        maxpool_split_kernel<<<grid, 256>>>(hs1, path_lens, ah, al);
    }

    // 9) h_f, t_f, query (split)
    gather_ht_kernel<<<BPq, 256>>>(feats, h_t_pairs, hf, tf, sh, sl);

    // 10-11) q/k/v projections
    split(mha_inW, w1h, w1l, (size_t)3 * BANKq * BANKq);
    gemm_bf16(sh, sl, w1h, w1l, mha_inb, qb, BPq, BANKq, BANKq, 0);
    gemm_bf16(ah, al, w1h + (size_t)BANKq * BANKq, w1l + (size_t)BANKq * BANKq,
              mha_inb + BANKq, kb, Mlstm, BANKq, BANKq, 0);
    gemm_bf16(ah, al, w1h + 2 * (size_t)BANKq * BANKq, w1l + 2 * (size_t)BANKq * BANKq,
              mha_inb + 2 * BANKq, vb, Mlstm, BANKq, BANKq, 0);

    // 12) tiny attention over K=3 paths (ctx split into sh/sl)
    mha_attn_kernel<<<BPq, 384>>>(qb, kb, vb, path_lens, rel_mask, sh, sl, validany);

    // 13) pinfo = ctx @ mha_outW^T + mha_outb
    split(mha_outW, w2h, w2l, (size_t)BANKq * BANKq);
    gemm_bf16(sh, sl, w2h, w2l, mha_outb, pinfo, BPq, BANKq, BANKq, 0);

    // 14) of (split into ah/al)
    build_of_split_kernel<<<BPq, 256>>>(hf, tf, pinfo, validany, ah, al);

    // 15) hid = relu(of @ pred_W + pred_b)
    gemm_bf16(ah, al, wph, wpl, pred_b, hid, BPq, BANK5q, BANK5q, 1);

    // 16) fused output heads
    head_kernel<<<BPq, 256>>>(hid, mW, mb, bW, bb, out);
}